// round 7
// baseline (speedup 1.0000x reference)
#include <cuda_runtime.h>
#include <math.h>

// ---------------- problem constants ----------------
#define BD     8          // batch
#define HEADS  8
#define DH     32         // dim head
#define CDIM   256        // model dim
#define FFI    1024       // ff inner
#define HW     4096       // 64*64 pixels
#define WID    64
#define NBH    64         // BD*HEADS
#define NKEY   256        // TOP_H * TOP_W

// ---------------- scratch (device globals: no allocs allowed) ----------------
__device__ float g_xn  [(long)BD*CDIM*HW];   // LN(x); reused for ff2 output
__device__ float g_qkv [(long)BD*768*HW];
__device__ float g_attn[(long)BD*CDIM*HW];
__device__ float g_cat [(long)BD*512*HW];
__device__ float g_ao  [(long)BD*CDIM*HW];
__device__ float g_h   [(long)BD*FFI*HW];
__device__ float g_hg  [(long)BD*FFI*HW];
__device__ float g_dwb [(long)BD*FFI*HW];
__device__ float g_kg  [NBH*DH*16*WID];
__device__ float g_vg  [NBH*DH*16*WID];
__device__ float g_kf  [NBH*NKEY*DH];
__device__ float g_vf  [NBH*NKEY*DH];
__device__ float g_qp  [NBH*DH];
__device__ float g_kh  [NBH*DH*WID];
__device__ int   g_topH[NBH*16];
__device__ int   g_topW[NBH*16];

// ---------------- channel layernorm (per pixel over 256 channels) ----------------
__global__ __launch_bounds__(256) void ln_kernel(const float* __restrict__ x,
                                                 const float* __restrict__ g,
                                                 const float* __restrict__ be,
                                                 float* __restrict__ out)
{
    int gp = blockIdx.x * 256 + threadIdx.x;           // 0..32767
    int b = gp >> 12, p = gp & 4095;
    const float* base = x + (long)b * CDIM * HW + p;
    float s = 0.f, s2 = 0.f;
    #pragma unroll 8
    for (int c = 0; c < CDIM; c++) { float v = base[(long)c * HW]; s += v; s2 += v * v; }
    float mean = s * (1.f / CDIM);
    float var  = s2 * (1.f / CDIM) - mean * mean;
    float inv  = rsqrtf(var + 1e-5f);
    float* ob = out + (long)b * CDIM * HW + p;
    #pragma unroll 8
    for (int c = 0; c < CDIM; c++) {
        float v = base[(long)c * HW];
        ob[(long)c * HW] = (v - mean) * inv * g[c] + be[c];
    }
}

// ---------------- generic SGEMM: C[z] = A(MxK) * B[z](KxN) (+bias)(+res) ----------------
// A row-major shared across batch; B/C/res batched by stride. M,N %128==0, K%8==0.
__global__ __launch_bounds__(256) void sgemm_kernel(
    const float* __restrict__ A, const float* __restrict__ B, float* __restrict__ C,
    int M, int N, int K, long strideB, long strideC,
    const float* __restrict__ bias, const float* __restrict__ res, long strideRes)
{
    __shared__ float As[8][128];
    __shared__ float Bs[8][128];
    int tid = threadIdx.x;
    const float* Bp = B + (long)blockIdx.z * strideB;
    float*       Cp = C + (long)blockIdx.z * strideC;
    int bx = blockIdx.x * 128, by = blockIdx.y * 128;
    int arow = tid >> 1, acol = (tid & 1) * 4;
    int brow = tid >> 5, bcol = (tid & 31) * 4;
    int tx = (tid & 15) * 8, ty = (tid >> 4) * 8;
    float acc[8][8];
    #pragma unroll
    for (int i = 0; i < 8; i++)
        #pragma unroll
        for (int j = 0; j < 8; j++) acc[i][j] = 0.f;
    const float* Ap = A + (long)(by + arow) * K + acol;
    const float* Bq = Bp + (long)brow * N + bx + bcol;
    for (int k0 = 0; k0 < K; k0 += 8) {
        float4 a4 = *(const float4*)(Ap + k0);
        As[acol + 0][arow] = a4.x; As[acol + 1][arow] = a4.y;
        As[acol + 2][arow] = a4.z; As[acol + 3][arow] = a4.w;
        *(float4*)&Bs[brow][bcol] = *(const float4*)(Bq + (long)k0 * N);
        __syncthreads();
        #pragma unroll
        for (int kk = 0; kk < 8; kk++) {
            float ar[8], br[8];
            *(float4*)&ar[0] = *(const float4*)&As[kk][ty];
            *(float4*)&ar[4] = *(const float4*)&As[kk][ty + 4];
            *(float4*)&br[0] = *(const float4*)&Bs[kk][tx];
            *(float4*)&br[4] = *(const float4*)&Bs[kk][tx + 4];
            #pragma unroll
            for (int i = 0; i < 8; i++)
                #pragma unroll
                for (int j = 0; j < 8; j++) acc[i][j] = fmaf(ar[i], br[j], acc[i][j]);
        }
        __syncthreads();
    }
    #pragma unroll
    for (int i = 0; i < 8; i++) {
        int row = by + ty + i;
        float bb = bias ? bias[row] : 0.f;
        long off = (long)row * N + bx + tx;
        if (res) {
            const float* rp = res + (long)blockIdx.z * strideRes + off;
            #pragma unroll
            for (int j = 0; j < 8; j++) Cp[off + j] = acc[i][j] + bb + rp[j];
        } else {
            #pragma unroll
            for (int j = 0; j < 8; j++) Cp[off + j] = acc[i][j] + bb;
        }
    }
}

// ---------------- l2-normalize q,k rows (along W=64) in place ----------------
// rows = 8 batches * 512 channels (q:0-255, k:256-511) * 64 h-rows
__global__ __launch_bounds__(256) void l2norm_kernel(float* __restrict__ qkv)
{
    int gt = blockIdx.x * 256 + threadIdx.x;
    int warp = gt >> 5, lane = gt & 31;
    if (warp >= BD * 512 * WID) return;
    int b = warp / (512 * WID);
    int rem = warp % (512 * WID);
    float* p = qkv + (long)b * 768 * HW + (long)rem * WID;
    float v0 = p[lane], v1 = p[lane + 32];
    float s = v0 * v0 + v1 * v1;
    #pragma unroll
    for (int o = 16; o > 0; o >>= 1) s += __shfl_xor_sync(0xffffffffu, s, o);
    float scale = 1.f / fmaxf(sqrtf(s), 1e-12f);
    p[lane] = v0 * scale; p[lane + 32] = v1 * scale;
}

// ---------------- q_probe[bh][d] = sum over all pixels of normalized q ----------------
__global__ __launch_bounds__(256) void qprobe_kernel(const float* __restrict__ qkv,
                                                     float* __restrict__ qp)
{
    __shared__ float sm[8];
    int c = blockIdx.x;                     // 0..2047 = bh*32+d
    int bh = c >> 5, d = c & 31, b = bh >> 3, hh = bh & 7;
    const float* p = qkv + (long)b * 768 * HW + (long)(hh * 32 + d) * HW;
    float s = 0.f;
    for (int i = threadIdx.x; i < HW; i += 256) s += p[i];
    #pragma unroll
    for (int o = 16; o > 0; o >>= 1) s += __shfl_xor_sync(0xffffffffu, s, o);
    if ((threadIdx.x & 31) == 0) sm[threadIdx.x >> 5] = s;
    __syncthreads();
    if (threadIdx.x == 0) { float t = 0; for (int i = 0; i < 8; i++) t += sm[i]; qp[c] = t; }
}

// ---------------- k_height[bh][d][h] = sum over w of normalized k ----------------
__global__ __launch_bounds__(256) void kheight_kernel(const float* __restrict__ qkv,
                                                      float* __restrict__ kh)
{
    int gt = blockIdx.x * 256 + threadIdx.x;
    int warp = gt >> 5, lane = gt & 31;
    if (warp >= NBH * DH * WID) return;
    int h = warp & 63; int rest = warp >> 6; int d = rest & 31; int bh = rest >> 5;
    int b = bh >> 3, hh = bh & 7;
    const float* p = qkv + (long)b * 768 * HW + (long)(256 + hh * 32 + d) * HW + h * WID;
    float s = p[lane] + p[lane + 32];
    #pragma unroll
    for (int o = 16; o > 0; o >>= 1) s += __shfl_xor_sync(0xffffffffu, s, o);
    if (lane == 0) kh[warp] = s;
}

// ---------------- score_r + top-16 rows (set only; order irrelevant downstream) ---------
__global__ void toph_kernel(const float* __restrict__ qp, const float* __restrict__ kh,
                            int* __restrict__ topH)
{
    __shared__ float sc[64]; __shared__ float qs[32];
    int bh = blockIdx.x, t = threadIdx.x;                  // 64 threads
    if (t < 32) qs[t] = qp[bh * 32 + t];
    __syncthreads();
    float s = 0.f;
    #pragma unroll
    for (int d = 0; d < 32; d++) s += qs[d] * kh[((bh * 32 + d) << 6) + t];
    sc[t] = s;
    __syncthreads();
    if (t == 0) {
        for (int it = 0; it < 16; it++) {
            float best = -3.4e38f; int bi = 0;
            for (int h = 0; h < 64; h++) if (sc[h] > best) { best = sc[h]; bi = h; }
            topH[bh * 16 + it] = bi; sc[bi] = -3.4e38f;
        }
    }
}

// ---------------- gather selected rows of k,v -> kg/vg [bh][d][16][64] -----------------
__global__ __launch_bounds__(256) void gather_rows_kernel(const float* __restrict__ qkv,
                                                          const int* __restrict__ topH,
                                                          float* __restrict__ kg,
                                                          float* __restrict__ vg)
{
    long i = (long)blockIdx.x * 256 + threadIdx.x;          // 64*32*16*64
    int w = i & 63; long r = i >> 6; int t = (int)(r & 15); r >>= 4;
    int d = (int)(r & 31); int bh = (int)(r >> 5);
    int b = bh >> 3, hh = bh & 7;
    int h = topH[bh * 16 + t];
    long base = (long)b * 768 * HW + (long)(hh * 32 + d) * HW + (long)h * WID + w;
    kg[i] = qkv[base + 256L * HW];
    vg[i] = qkv[base + 512L * HW];
}

// ---------------- score_c + top-16 columns ----------------
__global__ void topw_kernel(const float* __restrict__ qp, const float* __restrict__ kg,
                            int* __restrict__ topW)
{
    __shared__ float sc[64]; __shared__ float qs[32];
    int bh = blockIdx.x, t = threadIdx.x;                  // t = w, 64 threads
    if (t < 32) qs[t] = qp[bh * 32 + t];
    __syncthreads();
    float s = 0.f;
    for (int d = 0; d < 32; d++) {
        float colsum = 0.f;
        #pragma unroll
        for (int i = 0; i < 16; i++)
            colsum += kg[(((long)(bh * 32 + d) * 16) + i) * 64 + t];
        s += qs[d] * colsum;
    }
    sc[t] = s;
    __syncthreads();
    if (t == 0) {
        for (int it = 0; it < 16; it++) {
            float best = -3.4e38f; int bi = 0;
            for (int w = 0; w < 64; w++) if (sc[w] > best) { best = sc[w]; bi = w; }
            topW[bh * 16 + it] = bi; sc[bi] = -3.4e38f;
        }
    }
}

// ---------------- build kf/vf [bh][j][d], j = i*16 + jw ----------------
__global__ __launch_bounds__(256) void build_kv_kernel(const float* __restrict__ kg,
                                                       const float* __restrict__ vg,
                                                       const int* __restrict__ topW,
                                                       float* __restrict__ kf,
                                                       float* __restrict__ vf)
{
    long i = (long)blockIdx.x * 256 + threadIdx.x;          // 64*256*32
    int d = (int)(i & 31); long r = i >> 5; int j = (int)(r & 255); int bh = (int)(r >> 8);
    int ti = j >> 4, jw = j & 15;
    int w = topW[bh * 16 + jw];
    long src = (((long)(bh * 32 + d) * 16) + ti) * 64 + w;
    kf[i] = kg[src]; vf[i] = vg[src];
}

// ---------------- fused sparse attention: softmax(Q Kf^T) Vf ----------------
// one thread per query pixel; keys staged to smem in two 128-key chunks (32 KB).
// sim is bounded (l2-normalized inputs) -> max-free streaming softmax is exact.
__global__ __launch_bounds__(128) void attn_kernel(const float* __restrict__ qkv,
                                                   const float* __restrict__ kf,
                                                   const float* __restrict__ vf,
                                                   float* __restrict__ out)
{
    __shared__ float kfs[128 * 32];
    __shared__ float vfs[128 * 32];
    int bh = blockIdx.y;
    int b = bh >> 3, hh = bh & 7;
    int p = blockIdx.x * 128 + threadIdx.x;
    const float* qb = qkv + (long)b * 768 * HW + (long)(hh * 32) * HW + p;
    float q[32], acc[32];
    #pragma unroll
    for (int d = 0; d < 32; d++) { q[d] = qb[(long)d * HW]; acc[d] = 0.f; }
    float l = 0.f;
    for (int ch = 0; ch < 2; ch++) {
        const float4* kc = (const float4*)(kf + ((long)bh * NKEY + ch * 128) * 32);
        const float4* vc = (const float4*)(vf + ((long)bh * NKEY + ch * 128) * 32);
        for (int i = threadIdx.x; i < 1024; i += 128) {
            ((float4*)kfs)[i] = kc[i];
            ((float4*)vfs)[i] = vc[i];
        }
        __syncthreads();
        for (int j = 0; j < 128; j++) {
            const float4* k4 = (const float4*)&kfs[j * 32];
            float s = 0.f;
            #pragma unroll
            for (int d4 = 0; d4 < 8; d4++) {
                float4 kk = k4[d4];
                s += q[d4 * 4 + 0] * kk.x + q[d4 * 4 + 1] * kk.y
                   + q[d4 * 4 + 2] * kk.z + q[d4 * 4 + 3] * kk.w;
            }
            float e = __expf(s);
            l += e;
            const float4* v4 = (const float4*)&vfs[j * 32];
            #pragma unroll
            for (int d4 = 0; d4 < 8; d4++) {
                float4 vv = v4[d4];
                acc[d4 * 4 + 0] = fmaf(e, vv.x, acc[d4 * 4 + 0]);
                acc[d4 * 4 + 1] = fmaf(e, vv.y, acc[d4 * 4 + 1]);
                acc[d4 * 4 + 2] = fmaf(e, vv.z, acc[d4 * 4 + 2]);
                acc[d4 * 4 + 3] = fmaf(e, vv.w, acc[d4 * 4 + 3]);
            }
        }
        __syncthreads();
    }
    float inv = 1.f / l;
    float* ob = out + (long)b * CDIM * HW + (long)(hh * 32) * HW + p;
    #pragma unroll
    for (int d = 0; d < 32; d++) ob[(long)d * HW] = acc[d] * inv;
}

// ---------------- depthwise 3x3 SAME ----------------
__global__ __launch_bounds__(256) void dwconv_kernel(const float* __restrict__ in,
                                                     const float* __restrict__ w,
                                                     const float* __restrict__ bias,
                                                     float* __restrict__ out,
                                                     int C, long inBS, long outBS, int chanOff)
{
    int idx = blockIdx.x;
    int yt = idx & 15; idx >>= 4;
    int c = idx % C; int b = idx / C;
    int x = threadIdx.x & 63;
    int y = yt * 4 + (threadIdx.x >> 6);
    const float* ip = in + (long)b * inBS + (long)c * HW;
    const float* wp = w + c * 9;
    float s = bias[c];
    #pragma unroll
    for (int dy = 0; dy < 3; dy++) {
        int yy = y + dy - 1;
        if (yy < 0 || yy > 63) continue;
        #pragma unroll
        for (int dx = 0; dx < 3; dx++) {
            int xx = x + dx - 1;
            if (xx < 0 || xx > 63) continue;
            s += wp[dy * 3 + dx] * ip[yy * 64 + xx];
        }
    }
    out[(long)b * outBS + (long)(chanOff + c) * HW + y * 64 + x] = s;
}

// ---------------- instance norm (+gelu)(+add) : one block per (b,c) row of 4096 --------
__device__ __forceinline__ float gelu_exact(float u)
{
    return 0.5f * u * (1.f + erff(u * 0.7071067811865476f));
}

template <int MODE>  // 0: norm; 1: gelu(norm); 2: add + gelu(norm)
__global__ __launch_bounds__(256) void instnorm_kernel(const float* __restrict__ in,
                                                       const float* __restrict__ addsrc,
                                                       float* __restrict__ out)
{
    __shared__ float sm[16];
    long row = blockIdx.x;
    const float4* p = (const float4*)(in + row * HW);
    int t = threadIdx.x;
    float4 v[4];
    float s = 0.f, s2 = 0.f;
    #pragma unroll
    for (int i = 0; i < 4; i++) {
        v[i] = p[t + i * 256];
        s  += v[i].x + v[i].y + v[i].z + v[i].w;
        s2 += v[i].x * v[i].x + v[i].y * v[i].y + v[i].z * v[i].z + v[i].w * v[i].w;
    }
    #pragma unroll
    for (int o = 16; o > 0; o >>= 1) {
        s  += __shfl_xor_sync(0xffffffffu, s, o);
        s2 += __shfl_xor_sync(0xffffffffu, s2, o);
    }
    if ((t & 31) == 0) { sm[t >> 5] = s; sm[8 + (t >> 5)] = s2; }
    __syncthreads();
    if (t == 0) {
        float a = 0.f, b2 = 0.f;
        for (int i = 0; i < 8; i++) { a += sm[i]; b2 += sm[8 + i]; }
        sm[0] = a; sm[8] = b2;
    }
    __syncthreads();
    float mean = sm[0] * (1.f / HW);
    float var  = sm[8] * (1.f / HW) - mean * mean;
    float inv  = rsqrtf(var + 1e-5f);
    float4* op = (float4*)(out + row * HW);
    const float4* ap = (MODE == 2) ? (const float4*)(addsrc + row * HW) : nullptr;
    #pragma unroll
    for (int i = 0; i < 4; i++) {
        float4 u = v[i];
        u.x = (u.x - mean) * inv; u.y = (u.y - mean) * inv;
        u.z = (u.z - mean) * inv; u.w = (u.w - mean) * inv;
        if (MODE >= 1) {
            u.x = gelu_exact(u.x); u.y = gelu_exact(u.y);
            u.z = gelu_exact(u.z); u.w = gelu_exact(u.w);
        }
        if (MODE == 2) {
            float4 a = ap[t + i * 256];
            u.x += a.x; u.y += a.y; u.z += a.z; u.w += a.w;
        }
        op[t + i * 256] = u;
    }
}

// ---------------- host launcher ----------------
extern "C" void kernel_launch(void* const* d_in, const int* in_sizes, int n_in,
                              void* d_out, int out_size)
{
    (void)in_sizes; (void)n_in; (void)out_size;
    const float* x      = (const float*)d_in[0];
    const float* ln_g   = (const float*)d_in[1];
    const float* ln_b   = (const float*)d_in[2];
    const float* w_qkv  = (const float*)d_in[3];
    const float* w_out  = (const float*)d_in[4];
    const float* b_out  = (const float*)d_in[5];
    const float* w_dw   = (const float*)d_in[6];
    const float* b_dw   = (const float*)d_in[7];
    const float* w_comb = (const float*)d_in[8];
    const float* b_comb = (const float*)d_in[9];
    const float* w_ff1  = (const float*)d_in[10];
    const float* b_ff1  = (const float*)d_in[11];
    const float* w_ffdw = (const float*)d_in[12];
    const float* b_ffdw = (const float*)d_in[13];
    const float* w_ff2  = (const float*)d_in[14];
    const float* b_ff2  = (const float*)d_in[15];
    float* out = (float*)d_out;

    void *p;
    cudaGetSymbolAddress(&p, g_xn);   float* xn   = (float*)p;
    cudaGetSymbolAddress(&p, g_qkv);  float* qkv  = (float*)p;
    cudaGetSymbolAddress(&p, g_attn); float* attn = (float*)p;
    cudaGetSymbolAddress(&p, g_cat);  float* cat  = (float*)p;
    cudaGetSymbolAddress(&p, g_ao);   float* ao   = (float*)p;
    cudaGetSymbolAddress(&p, g_h);    float* h    = (float*)p;
    cudaGetSymbolAddress(&p, g_hg);   float* hg   = (float*)p;
    cudaGetSymbolAddress(&p, g_dwb);  float* dwb  = (float*)p;
    cudaGetSymbolAddress(&p, g_kg);   float* kg   = (float*)p;
    cudaGetSymbolAddress(&p, g_vg);   float* vg   = (float*)p;
    cudaGetSymbolAddress(&p, g_kf);   float* kf   = (float*)p;
    cudaGetSymbolAddress(&p, g_vf);   float* vf   = (float*)p;
    cudaGetSymbolAddress(&p, g_qp);   float* qp   = (float*)p;
    cudaGetSymbolAddress(&p, g_kh);   float* kh   = (float*)p;
    cudaGetSymbolAddress(&p, g_topH); int*   topH = (int*)p;
    cudaGetSymbolAddress(&p, g_topW); int*   topW = (int*)p;

    // 1. channel layernorm
    ln_kernel<<<128, 256>>>(x, ln_g, ln_b, xn);
    // 2. qkv projection (768x256 @ 256x4096, per batch)
    sgemm_kernel<<<dim3(32, 6, BD), 256>>>(w_qkv, xn, qkv, 768, HW, 256,
                                           (long)CDIM * HW, (long)768 * HW,
                                           nullptr, nullptr, 0);
    // 3. l2-normalize q,k along W (in place)
    l2norm_kernel<<<32768, 256>>>(qkv);
    // 4. probes + top-k selection
    qprobe_kernel<<<2048, 256>>>(qkv, qp);
    kheight_kernel<<<16384, 256>>>(qkv, kh);
    toph_kernel<<<64, 64>>>(qp, kh, topH);
    gather_rows_kernel<<<8192, 256>>>(qkv, topH, kg, vg);
    topw_kernel<<<64, 64>>>(qp, kg, topW);
    build_kv_kernel<<<2048, 256>>>(kg, vg, topW, kf, vf);
    // 5. fused sparse attention
    attn_kernel<<<dim3(32, NBH), 128>>>(qkv, kf, vf, attn);
    // 6. out-proj into concat buffer rows [0,256)
    sgemm_kernel<<<dim3(32, 2, BD), 256>>>(w_out, attn, cat, 256, HW, 256,
                                           (long)CDIM * HW, (long)512 * HW,
                                           b_out, nullptr, 0);
    // 7. dwconv branch into concat buffer rows [256,512)
    dwconv_kernel<<<BD * 256 * 16, 256>>>(x, w_dw, b_dw, cat, 256,
                                          (long)CDIM * HW, (long)512 * HW, 256);
    // 8. combine (K=512) + bias + residual x
    sgemm_kernel<<<dim3(32, 2, BD), 256>>>(w_comb, cat, ao, 256, HW, 512,
                                           (long)512 * HW, (long)CDIM * HW,
                                           b_comb, x, (long)CDIM * HW);
    // 9. ff1
    sgemm_kernel<<<dim3(32, 8, BD), 256>>>(w_ff1, ao, h, FFI, HW, 256,
                                           (long)CDIM * HW, (long)FFI * HW,
                                           b_ff1, nullptr, 0);
    // 10. h = gelu(instnorm(h))
    instnorm_kernel<1><<<BD * FFI, 256>>>(h, nullptr, hg);
    // 11. dwconv(ffdw)
    dwconv_kernel<<<BD * FFI * 16, 256>>>(hg, w_ffdw, b_ffdw, dwb, FFI,
                                          (long)FFI * HW, (long)FFI * HW, 0);
    // 12. h = hg + gelu(instnorm(dw))
    instnorm_kernel<2><<<BD * FFI, 256>>>(dwb, hg, h);
    // 13. ff2 (reuse xn buffer for output)
    sgemm_kernel<<<dim3(32, 2, BD), 256>>>(w_ff2, h, xn, 256, HW, FFI,
                                           (long)FFI * HW, (long)CDIM * HW,
                                           b_ff2, nullptr, 0);
    // 14. final instance norm -> d_out
    instnorm_kernel<0><<<BD * CDIM, 256>>>(xn, nullptr, out);
}

// round 8
// speedup vs baseline: 1.2535x; 1.2535x over previous
#include <cuda_runtime.h>
#include <math.h>
#include <stdint.h>

// ---------------- problem constants ----------------
#define BD     8          // batch
#define HEADS  8
#define DH     32         // dim head
#define CDIM   256        // model dim
#define FFI    1024       // ff inner
#define HW     4096       // 64*64 pixels
#define WID    64
#define NBH    64         // BD*HEADS
#define NKEY   256        // TOP_H * TOP_W

// ---------------- scratch (device globals: no allocs allowed) ----------------
__device__ float g_xn  [(long)BD*CDIM*HW];   // LN(x); reused for ff2 output
__device__ float g_qkv [(long)BD*768*HW];
__device__ float g_attn[(long)BD*CDIM*HW];
__device__ float g_cat [(long)BD*512*HW];
__device__ float g_ao  [(long)BD*CDIM*HW];
__device__ float g_h   [(long)BD*FFI*HW];
__device__ float g_hg  [(long)BD*FFI*HW];
__device__ float g_dwb [(long)BD*FFI*HW];
__device__ float g_kg  [NBH*DH*16*WID];
__device__ float g_vg  [NBH*DH*16*WID];
__device__ float g_kf  [NBH*NKEY*DH];
__device__ float g_vf  [NBH*NKEY*DH];
__device__ float g_qp  [NBH*DH];
__device__ float g_kh  [NBH*DH*WID];
__device__ int   g_topH[NBH*16];
__device__ int   g_topW[NBH*16];

// ---------------- channel layernorm (per pixel over 256 channels) ----------------
__global__ __launch_bounds__(256) void ln_kernel(const float* __restrict__ x,
                                                 const float* __restrict__ g,
                                                 const float* __restrict__ be,
                                                 float* __restrict__ out)
{
    int gp = blockIdx.x * 256 + threadIdx.x;           // 0..32767
    int b = gp >> 12, p = gp & 4095;
    const float* base = x + (long)b * CDIM * HW + p;
    float s = 0.f, s2 = 0.f;
    #pragma unroll 8
    for (int c = 0; c < CDIM; c++) { float v = base[(long)c * HW]; s += v; s2 += v * v; }
    float mean = s * (1.f / CDIM);
    float var  = s2 * (1.f / CDIM) - mean * mean;
    float inv  = rsqrtf(var + 1e-5f);
    float* ob = out + (long)b * CDIM * HW + p;
    #pragma unroll 8
    for (int c = 0; c < CDIM; c++) {
        float v = base[(long)c * HW];
        ob[(long)c * HW] = (v - mean) * inv * g[c] + be[c];
    }
}

// ---------------- TF32x3 tensor-core GEMM ----------------
// C[z] = A(MxK) * B[z](KxN) (+bias)(+res).  A row-major shared across batch;
// B/C/res batched by stride.  M,N %128==0, K %16==0.
// 128x128 block tile, 8 warps (2x4), 64x32 warp tile, m16n8k8 tf32 mma.
// 3xTF32: a=a_big+a_small, product = bb + bs + sb (ss dropped, ~2^-22 rel).

__device__ __forceinline__ uint32_t f2tf(float x)
{
    uint32_t r;
    asm("cvt.rna.tf32.f32 %0, %1;" : "=r"(r) : "f"(x));
    return r;
}

#define MMA_TF32(c, a, b) \
    asm volatile("mma.sync.aligned.m16n8k8.row.col.f32.tf32.tf32.f32 " \
        "{%0,%1,%2,%3}, {%4,%5,%6,%7}, {%8,%9}, {%0,%1,%2,%3};" \
        : "+f"((c)[0]), "+f"((c)[1]), "+f"((c)[2]), "+f"((c)[3]) \
        : "r"((a)[0]), "r"((a)[1]), "r"((a)[2]), "r"((a)[3]), \
          "r"((b)[0]), "r"((b)[1]))

__global__ __launch_bounds__(256) void tgemm_kernel(
    const float* __restrict__ A, const float* __restrict__ B, float* __restrict__ C,
    int M, int N, int K, long strideB, long strideC,
    const float* __restrict__ bias, const float* __restrict__ res, long strideRes)
{
    __shared__ uint32_t AsB[128][20], AsS[128][20];   // [m][k], pad->conflict-free frag ld
    __shared__ uint32_t BsB[16][136], BsS[16][136];   // [k][n], pad 136
    int tid = threadIdx.x;
    int lane = tid & 31, warp = tid >> 5;
    int wm = (warp >> 2) * 64, wn = (warp & 3) * 32;
    int bx = blockIdx.x * 128, by = blockIdx.y * 128;
    const float* Bp = B + (long)blockIdx.z * strideB;
    float*       Cp = C + (long)blockIdx.z * strideC;

    float acc[4][4][4];
    #pragma unroll
    for (int i = 0; i < 4; i++)
        #pragma unroll
        for (int j = 0; j < 4; j++)
            #pragma unroll
            for (int k = 0; k < 4; k++) acc[i][j][k] = 0.f;

    // register prefetch of tile 0
    float4 pa[2], pb[2];
    #pragma unroll
    for (int u = 0; u < 2; u++) {
        int idx = tid + u * 256;
        pa[u] = *(const float4*)(A  + (long)(by + (idx >> 2)) * K + (idx & 3) * 4);
        pb[u] = *(const float4*)(Bp + (long)(idx >> 5) * N + bx + (idx & 31) * 4);
    }

    int nIter = K >> 4;
    for (int it = 0; it < nIter; it++) {
        // stage current tile into smem with big/small split
        #pragma unroll
        for (int u = 0; u < 2; u++) {
            int idx = tid + u * 256;
            int ar = idx >> 2, ac = (idx & 3) * 4;
            float av[4] = { pa[u].x, pa[u].y, pa[u].z, pa[u].w };
            #pragma unroll
            for (int j = 0; j < 4; j++) {
                uint32_t big = f2tf(av[j]);
                AsB[ar][ac + j] = big;
                AsS[ar][ac + j] = f2tf(av[j] - __uint_as_float(big));
            }
            int br = idx >> 5, bc = (idx & 31) * 4;
            float bv[4] = { pb[u].x, pb[u].y, pb[u].z, pb[u].w };
            uint32_t bigv[4], smlv[4];
            #pragma unroll
            for (int j = 0; j < 4; j++) {
                bigv[j] = f2tf(bv[j]);
                smlv[j] = f2tf(bv[j] - __uint_as_float(bigv[j]));
            }
            *(uint4*)&BsB[br][bc] = make_uint4(bigv[0], bigv[1], bigv[2], bigv[3]);
            *(uint4*)&BsS[br][bc] = make_uint4(smlv[0], smlv[1], smlv[2], smlv[3]);
        }
        __syncthreads();
        // prefetch next tile (global loads overlap compute below)
        if (it + 1 < nIter) {
            int k0 = (it + 1) << 4;
            #pragma unroll
            for (int u = 0; u < 2; u++) {
                int idx = tid + u * 256;
                pa[u] = *(const float4*)(A  + (long)(by + (idx >> 2)) * K + k0 + (idx & 3) * 4);
                pb[u] = *(const float4*)(Bp + (long)(k0 + (idx >> 5)) * N + bx + (idx & 31) * 4);
            }
        }
        // compute: 2 k-steps of 8
        #pragma unroll
        for (int ks = 0; ks < 2; ks++) {
            int kb = ks * 8;
            int mr = lane >> 2, kc = lane & 3;
            uint32_t aB[4][4], aS[4][4], bB[4][2], bS[4][2];
            #pragma unroll
            for (int mt = 0; mt < 4; mt++) {
                int m = wm + mt * 16 + mr;
                aB[mt][0] = AsB[m][kb + kc];     aB[mt][1] = AsB[m + 8][kb + kc];
                aB[mt][2] = AsB[m][kb + kc + 4]; aB[mt][3] = AsB[m + 8][kb + kc + 4];
                aS[mt][0] = AsS[m][kb + kc];     aS[mt][1] = AsS[m + 8][kb + kc];
                aS[mt][2] = AsS[m][kb + kc + 4]; aS[mt][3] = AsS[m + 8][kb + kc + 4];
            }
            #pragma unroll
            for (int nt = 0; nt < 4; nt++) {
                int n = wn + nt * 8 + mr;
                bB[nt][0] = BsB[kb + kc][n]; bB[nt][1] = BsB[kb + kc + 4][n];
                bS[nt][0] = BsS[kb + kc][n]; bS[nt][1] = BsS[kb + kc + 4][n];
            }
            #pragma unroll
            for (int mt = 0; mt < 4; mt++)
                #pragma unroll
                for (int nt = 0; nt < 4; nt++) MMA_TF32(acc[mt][nt], aB[mt], bB[nt]);
            #pragma unroll
            for (int mt = 0; mt < 4; mt++)
                #pragma unroll
                for (int nt = 0; nt < 4; nt++) MMA_TF32(acc[mt][nt], aB[mt], bS[nt]);
            #pragma unroll
            for (int mt = 0; mt < 4; mt++)
                #pragma unroll
                for (int nt = 0; nt < 4; nt++) MMA_TF32(acc[mt][nt], aS[mt], bB[nt]);
        }
        __syncthreads();
    }
    // epilogue
    int mr = lane >> 2, qc = (lane & 3) * 2;
    #pragma unroll
    for (int mt = 0; mt < 4; mt++) {
        int r0 = by + wm + mt * 16 + mr;
        float bb0 = bias ? bias[r0] : 0.f;
        float bb1 = bias ? bias[r0 + 8] : 0.f;
        #pragma unroll
        for (int nt = 0; nt < 4; nt++) {
            int c = bx + wn + nt * 8 + qc;
            long o0 = (long)r0 * N + c;
            long o1 = (long)(r0 + 8) * N + c;
            float2 v0 = make_float2(acc[mt][nt][0] + bb0, acc[mt][nt][1] + bb0);
            float2 v1 = make_float2(acc[mt][nt][2] + bb1, acc[mt][nt][3] + bb1);
            if (res) {
                const float* rp = res + (long)blockIdx.z * strideRes;
                v0.x += rp[o0]; v0.y += rp[o0 + 1];
                v1.x += rp[o1]; v1.y += rp[o1 + 1];
            }
            *(float2*)&Cp[o0] = v0;
            *(float2*)&Cp[o1] = v1;
        }
    }
}

// ---------------- l2-normalize q,k rows (along W=64) in place ----------------
__global__ __launch_bounds__(256) void l2norm_kernel(float* __restrict__ qkv)
{
    int gt = blockIdx.x * 256 + threadIdx.x;
    int warp = gt >> 5, lane = gt & 31;
    if (warp >= BD * 512 * WID) return;
    int b = warp / (512 * WID);
    int rem = warp % (512 * WID);
    float* p = qkv + (long)b * 768 * HW + (long)rem * WID;
    float v0 = p[lane], v1 = p[lane + 32];
    float s = v0 * v0 + v1 * v1;
    #pragma unroll
    for (int o = 16; o > 0; o >>= 1) s += __shfl_xor_sync(0xffffffffu, s, o);
    float scale = 1.f / fmaxf(sqrtf(s), 1e-12f);
    p[lane] = v0 * scale; p[lane + 32] = v1 * scale;
}

// ---------------- q_probe[bh][d] = sum over all pixels of normalized q ----------------
__global__ __launch_bounds__(256) void qprobe_kernel(const float* __restrict__ qkv,
                                                     float* __restrict__ qp)
{
    __shared__ float sm[8];
    int c = blockIdx.x;                     // 0..2047 = bh*32+d
    int bh = c >> 5, d = c & 31, b = bh >> 3, hh = bh & 7;
    const float* p = qkv + (long)b * 768 * HW + (long)(hh * 32 + d) * HW;
    float s = 0.f;
    for (int i = threadIdx.x; i < HW; i += 256) s += p[i];
    #pragma unroll
    for (int o = 16; o > 0; o >>= 1) s += __shfl_xor_sync(0xffffffffu, s, o);
    if ((threadIdx.x & 31) == 0) sm[threadIdx.x >> 5] = s;
    __syncthreads();
    if (threadIdx.x == 0) { float t = 0; for (int i = 0; i < 8; i++) t += sm[i]; qp[c] = t; }
}

// ---------------- k_height[bh][d][h] = sum over w of normalized k ----------------
__global__ __launch_bounds__(256) void kheight_kernel(const float* __restrict__ qkv,
                                                      float* __restrict__ kh)
{
    int gt = blockIdx.x * 256 + threadIdx.x;
    int warp = gt >> 5, lane = gt & 31;
    if (warp >= NBH * DH * WID) return;
    int h = warp & 63; int rest = warp >> 6; int d = rest & 31; int bh = rest >> 5;
    int b = bh >> 3, hh = bh & 7;
    const float* p = qkv + (long)b * 768 * HW + (long)(256 + hh * 32 + d) * HW + h * WID;
    float s = p[lane] + p[lane + 32];
    #pragma unroll
    for (int o = 16; o > 0; o >>= 1) s += __shfl_xor_sync(0xffffffffu, s, o);
    if (lane == 0) kh[warp] = s;
}

// ---------------- score_r + top-16 rows (set only; order irrelevant downstream) ---------
__global__ void toph_kernel(const float* __restrict__ qp, const float* __restrict__ kh,
                            int* __restrict__ topH)
{
    __shared__ float sc[64]; __shared__ float qs[32];
    int bh = blockIdx.x, t = threadIdx.x;                  // 64 threads
    if (t < 32) qs[t] = qp[bh * 32 + t];
    __syncthreads();
    float s = 0.f;
    #pragma unroll
    for (int d = 0; d < 32; d++) s += qs[d] * kh[((bh * 32 + d) << 6) + t];
    sc[t] = s;
    __syncthreads();
    if (t == 0) {
        for (int it = 0; it < 16; it++) {
            float best = -3.4e38f; int bi = 0;
            for (int h = 0; h < 64; h++) if (sc[h] > best) { best = sc[h]; bi = h; }
            topH[bh * 16 + it] = bi; sc[bi] = -3.4e38f;
        }
    }
}

// ---------------- gather selected rows of k,v -> kg/vg [bh][d][16][64] -----------------
__global__ __launch_bounds__(256) void gather_rows_kernel(const float* __restrict__ qkv,
                                                          const int* __restrict__ topH,
                                                          float* __restrict__ kg,
                                                          float* __restrict__ vg)
{
    long i = (long)blockIdx.x * 256 + threadIdx.x;          // 64*32*16*64
    int w = i & 63; long r = i >> 6; int t = (int)(r & 15); r >>= 4;
    int d = (int)(r & 31); int bh = (int)(r >> 5);
    int b = bh >> 3, hh = bh & 7;
    int h = topH[bh * 16 + t];
    long base = (long)b * 768 * HW + (long)(hh * 32 + d) * HW + (long)h * WID + w;
    kg[i] = qkv[base + 256L * HW];
    vg[i] = qkv[base + 512L * HW];
}

// ---------------- score_c + top-16 columns ----------------
__global__ void topw_kernel(const float* __restrict__ qp, const float* __restrict__ kg,
                            int* __restrict__ topW)
{
    __shared__ float sc[64]; __shared__ float qs[32];
    int bh = blockIdx.x, t = threadIdx.x;                  // t = w, 64 threads
    if (t < 32) qs[t] = qp[bh * 32 + t];
    __syncthreads();
    float s = 0.f;
    for (int d = 0; d < 32; d++) {
        float colsum = 0.f;
        #pragma unroll
        for (int i = 0; i < 16; i++)
            colsum += kg[(((long)(bh * 32 + d) * 16) + i) * 64 + t];
        s += qs[d] * colsum;
    }
    sc[t] = s;
    __syncthreads();
    if (t == 0) {
        for (int it = 0; it < 16; it++) {
            float best = -3.4e38f; int bi = 0;
            for (int w = 0; w < 64; w++) if (sc[w] > best) { best = sc[w]; bi = w; }
            topW[bh * 16 + it] = bi; sc[bi] = -3.4e38f;
        }
    }
}

// ---------------- build kf/vf [bh][j][d], j = i*16 + jw ----------------
__global__ __launch_bounds__(256) void build_kv_kernel(const float* __restrict__ kg,
                                                       const float* __restrict__ vg,
                                                       const int* __restrict__ topW,
                                                       float* __restrict__ kf,
                                                       float* __restrict__ vf)
{
    long i = (long)blockIdx.x * 256 + threadIdx.x;          // 64*256*32
    int d = (int)(i & 31); long r = i >> 5; int j = (int)(r & 255); int bh = (int)(r >> 8);
    int ti = j >> 4, jw = j & 15;
    int w = topW[bh * 16 + jw];
    long src = (((long)(bh * 32 + d) * 16) + ti) * 64 + w;
    kf[i] = kg[src]; vf[i] = vg[src];
}

// ---------------- fused sparse attention: softmax(Q Kf^T) Vf ----------------
__global__ __launch_bounds__(128) void attn_kernel(const float* __restrict__ qkv,
                                                   const float* __restrict__ kf,
                                                   const float* __restrict__ vf,
                                                   float* __restrict__ out)
{
    __shared__ float kfs[128 * 32];
    __shared__ float vfs[128 * 32];
    int bh = blockIdx.y;
    int b = bh >> 3, hh = bh & 7;
    int p = blockIdx.x * 128 + threadIdx.x;
    const float* qb = qkv + (long)b * 768 * HW + (long)(hh * 32) * HW + p;
    float q[32], acc[32];
    #pragma unroll
    for (int d = 0; d < 32; d++) { q[d] = qb[(long)d * HW]; acc[d] = 0.f; }
    float l = 0.f;
    for (int ch = 0; ch < 2; ch++) {
        const float4* kc = (const float4*)(kf + ((long)bh * NKEY + ch * 128) * 32);
        const float4* vc = (const float4*)(vf + ((long)bh * NKEY + ch * 128) * 32);
        for (int i = threadIdx.x; i < 1024; i += 128) {
            ((float4*)kfs)[i] = kc[i];
            ((float4*)vfs)[i] = vc[i];
        }
        __syncthreads();
        for (int j = 0; j < 128; j++) {
            const float4* k4 = (const float4*)&kfs[j * 32];
            float s = 0.f;
            #pragma unroll
            for (int d4 = 0; d4 < 8; d4++) {
                float4 kk = k4[d4];
                s += q[d4 * 4 + 0] * kk.x + q[d4 * 4 + 1] * kk.y
                   + q[d4 * 4 + 2] * kk.z + q[d4 * 4 + 3] * kk.w;
            }
            float e = __expf(s);
            l += e;
            const float4* v4 = (const float4*)&vfs[j * 32];
            #pragma unroll
            for (int d4 = 0; d4 < 8; d4++) {
                float4 vv = v4[d4];
                acc[d4 * 4 + 0] = fmaf(e, vv.x, acc[d4 * 4 + 0]);
                acc[d4 * 4 + 1] = fmaf(e, vv.y, acc[d4 * 4 + 1]);
                acc[d4 * 4 + 2] = fmaf(e, vv.z, acc[d4 * 4 + 2]);
                acc[d4 * 4 + 3] = fmaf(e, vv.w, acc[d4 * 4 + 3]);
            }
        }
        __syncthreads();
    }
    float inv = 1.f / l;
    float* ob = out + (long)b * CDIM * HW + (long)(hh * 32) * HW + p;
    #pragma unroll
    for (int d = 0; d < 32; d++) ob[(long)d * HW] = acc[d] * inv;
}

// ---------------- depthwise 3x3 SAME ----------------
__global__ __launch_bounds__(256) void dwconv_kernel(const float* __restrict__ in,
                                                     const float* __restrict__ w,
                                                     const float* __restrict__ bias,
                                                     float* __restrict__ out,
                                                     int C, long inBS, long outBS, int chanOff)
{
    int idx = blockIdx.x;
    int yt = idx & 15; idx >>= 4;
    int c = idx % C; int b = idx / C;
    int x = threadIdx.x & 63;
    int y = yt * 4 + (threadIdx.x >> 6);
    const float* ip = in + (long)b * inBS + (long)c * HW;
    const float* wp = w + c * 9;
    float s = bias[c];
    #pragma unroll
    for (int dy = 0; dy < 3; dy++) {
        int yy = y + dy - 1;
        if (yy < 0 || yy > 63) continue;
        #pragma unroll
        for (int dx = 0; dx < 3; dx++) {
            int xx = x + dx - 1;
            if (xx < 0 || xx > 63) continue;
            s += wp[dy * 3 + dx] * ip[yy * 64 + xx];
        }
    }
    out[(long)b * outBS + (long)(chanOff + c) * HW + y * 64 + x] = s;
}

// ---------------- instance norm (+gelu)(+add) ----------------
__device__ __forceinline__ float gelu_exact(float u)
{
    return 0.5f * u * (1.f + erff(u * 0.7071067811865476f));
}

template <int MODE>  // 0: norm; 1: gelu(norm); 2: add + gelu(norm)
__global__ __launch_bounds__(256) void instnorm_kernel(const float* __restrict__ in,
                                                       const float* __restrict__ addsrc,
                                                       float* __restrict__ out)
{
    __shared__ float sm[16];
    long row = blockIdx.x;
    const float4* p = (const float4*)(in + row * HW);
    int t = threadIdx.x;
    float4 v[4];
    float s = 0.f, s2 = 0.f;
    #pragma unroll
    for (int i = 0; i < 4; i++) {
        v[i] = p[t + i * 256];
        s  += v[i].x + v[i].y + v[i].z + v[i].w;
        s2 += v[i].x * v[i].x + v[i].y * v[i].y + v[i].z * v[i].z + v[i].w * v[i].w;
    }
    #pragma unroll
    for (int o = 16; o > 0; o >>= 1) {
        s  += __shfl_xor_sync(0xffffffffu, s, o);
        s2 += __shfl_xor_sync(0xffffffffu, s2, o);
    }
    if ((t & 31) == 0) { sm[t >> 5] = s; sm[8 + (t >> 5)] = s2; }
    __syncthreads();
    if (t == 0) {
        float a = 0.f, b2 = 0.f;
        for (int i = 0; i < 8; i++) { a += sm[i]; b2 += sm[8 + i]; }
        sm[0] = a; sm[8] = b2;
    }
    __syncthreads();
    float mean = sm[0] * (1.f / HW);
    float var  = sm[8] * (1.f / HW) - mean * mean;
    float inv  = rsqrtf(var + 1e-5f);
    float4* op = (float4*)(out + row * HW);
    const float4* ap = (MODE == 2) ? (const float4*)(addsrc + row * HW) : nullptr;
    #pragma unroll
    for (int i = 0; i < 4; i++) {
        float4 u = v[i];
        u.x = (u.x - mean) * inv; u.y = (u.y - mean) * inv;
        u.z = (u.z - mean) * inv; u.w = (u.w - mean) * inv;
        if (MODE >= 1) {
            u.x = gelu_exact(u.x); u.y = gelu_exact(u.y);
            u.z = gelu_exact(u.z); u.w = gelu_exact(u.w);
        }
        if (MODE == 2) {
            float4 a = ap[t + i * 256];
            u.x += a.x; u.y += a.y; u.z += a.z; u.w += a.w;
        }
        op[t + i * 256] = u;
    }
}

// ---------------- host launcher ----------------
extern "C" void kernel_launch(void* const* d_in, const int* in_sizes, int n_in,
                              void* d_out, int out_size)
{
    (void)in_sizes; (void)n_in; (void)out_size;
    const float* x      = (const float*)d_in[0];
    const float* ln_g   = (const float*)d_in[1];
    const float* ln_b   = (const float*)d_in[2];
    const float* w_qkv  = (const float*)d_in[3];
    const float* w_out  = (const float*)d_in[4];
    const float* b_out  = (const float*)d_in[5];
    const float* w_dw   = (const float*)d_in[6];
    const float* b_dw   = (const float*)d_in[7];
    const float* w_comb = (const float*)d_in[8];
    const float* b_comb = (const float*)d_in[9];
    const float* w_ff1  = (const float*)d_in[10];
    const float* b_ff1  = (const float*)d_in[11];
    const float* w_ffdw = (const float*)d_in[12];
    const float* b_ffdw = (const float*)d_in[13];
    const float* w_ff2  = (const float*)d_in[14];
    const float* b_ff2  = (const float*)d_in[15];
    float* out = (float*)d_out;

    void *p;
    cudaGetSymbolAddress(&p, g_xn);   float* xn   = (float*)p;
    cudaGetSymbolAddress(&p, g_qkv);  float* qkv  = (float*)p;
    cudaGetSymbolAddress(&p, g_attn); float* attn = (float*)p;
    cudaGetSymbolAddress(&p, g_cat);  float* cat  = (float*)p;
    cudaGetSymbolAddress(&p, g_ao);   float* ao   = (float*)p;
    cudaGetSymbolAddress(&p, g_h);    float* h    = (float*)p;
    cudaGetSymbolAddress(&p, g_hg);   float* hg   = (float*)p;
    cudaGetSymbolAddress(&p, g_dwb);  float* dwb  = (float*)p;
    cudaGetSymbolAddress(&p, g_kg);   float* kg   = (float*)p;
    cudaGetSymbolAddress(&p, g_vg);   float* vg   = (float*)p;
    cudaGetSymbolAddress(&p, g_kf);   float* kf   = (float*)p;
    cudaGetSymbolAddress(&p, g_vf);   float* vf   = (float*)p;
    cudaGetSymbolAddress(&p, g_qp);   float* qp   = (float*)p;
    cudaGetSymbolAddress(&p, g_kh);   float* kh   = (float*)p;
    cudaGetSymbolAddress(&p, g_topH); int*   topH = (int*)p;
    cudaGetSymbolAddress(&p, g_topW); int*   topW = (int*)p;

    // 1. channel layernorm
    ln_kernel<<<128, 256>>>(x, ln_g, ln_b, xn);
    // 2. qkv projection (768x256 @ 256x4096, per batch)
    tgemm_kernel<<<dim3(32, 6, BD), 256>>>(w_qkv, xn, qkv, 768, HW, 256,
                                           (long)CDIM * HW, (long)768 * HW,
                                           nullptr, nullptr, 0);
    // 3. l2-normalize q,k along W (in place)
    l2norm_kernel<<<32768, 256>>>(qkv);
    // 4. probes + top-k selection
    qprobe_kernel<<<2048, 256>>>(qkv, qp);
    kheight_kernel<<<16384, 256>>>(qkv, kh);
    toph_kernel<<<64, 64>>>(qp, kh, topH);
    gather_rows_kernel<<<8192, 256>>>(qkv, topH, kg, vg);
    topw_kernel<<<64, 64>>>(qp, kg, topW);
    build_kv_kernel<<<2048, 256>>>(kg, vg, topW, kf, vf);
    // 5. fused sparse attention
    attn_kernel<<<dim3(32, NBH), 128>>>(qkv, kf, vf, attn);
    // 6. out-proj into concat buffer rows [0,256)
    tgemm_kernel<<<dim3(32, 2, BD), 256>>>(w_out, attn, cat, 256, HW, 256,
                                           (long)CDIM * HW, (long)512 * HW,
                                           b_out, nullptr, 0);
    // 7. dwconv branch into concat buffer rows [256,512)
    dwconv_kernel<<<BD * 256 * 16, 256>>>(x, w_dw, b_dw, cat, 256,
                                          (long)CDIM * HW, (long)512 * HW, 256);
    // 8. combine (K=512) + bias + residual x
    tgemm_kernel<<<dim3(32, 2, BD), 256>>>(w_comb, cat, ao, 256, HW, 512,
                                           (long)512 * HW, (long)CDIM * HW,
                                           b_comb, x, (long)CDIM * HW);
    // 9. ff1
    tgemm_kernel<<<dim3(32, 8, BD), 256>>>(w_ff1, ao, h, FFI, HW, 256,
                                           (long)CDIM * HW, (long)FFI * HW,
                                           b_ff1, nullptr, 0);
    // 10. h = gelu(instnorm(h))
    instnorm_kernel<1><<<BD * FFI, 256>>>(h, nullptr, hg);
    // 11. dwconv(ffdw)
    dwconv_kernel<<<BD * FFI * 16, 256>>>(hg, w_ffdw, b_ffdw, dwb, FFI,
                                          (long)FFI * HW, (long)FFI * HW, 0);
    // 12. h = hg + gelu(instnorm(dw))
    instnorm_kernel<2><<<BD * FFI, 256>>>(dwb, hg, h);
    // 13. ff2 (reuse xn buffer for output)
    tgemm_kernel<<<dim3(32, 2, BD), 256>>>(w_ff2, h, xn, 256, HW, 1024,
                                           (long)FFI * HW, (long)CDIM * HW,
                                           b_ff2, nullptr, 0);
    // 14. final instance norm -> d_out
    instnorm_kernel<0><<<BD * CDIM, 256>>>(xn, nullptr, out);
}

// round 9
// speedup vs baseline: 1.2880x; 1.0275x over previous
#include <cuda_runtime.h>
#include <math.h>
#include <stdint.h>

// ---------------- problem constants ----------------
#define BD     8          // batch
#define HEADS  8
#define DH     32         // dim head
#define CDIM   256        // model dim
#define FFI    1024       // ff inner
#define HW     4096       // 64*64 pixels
#define WID    64
#define NBH    64         // BD*HEADS
#define NKEY   256        // TOP_H * TOP_W

// ---------------- scratch (device globals: no allocs allowed) ----------------
__device__ float g_xn  [(long)BD*CDIM*HW];   // LN(x); reused for ff2 output
__device__ float g_qkv [(long)BD*768*HW];
__device__ float g_attn[(long)BD*CDIM*HW];
__device__ float g_cat [(long)BD*512*HW];
__device__ float g_ao  [(long)BD*CDIM*HW];
__device__ float g_h   [(long)BD*FFI*HW];
__device__ float g_hg  [(long)BD*FFI*HW];
__device__ float g_dwb [(long)BD*FFI*HW];
__device__ float g_kg  [NBH*DH*16*WID];
__device__ float g_vg  [NBH*DH*16*WID];
__device__ float g_kf  [NBH*NKEY*DH];
__device__ float g_vf  [NBH*NKEY*DH];
__device__ float g_qp  [NBH*DH];
__device__ float g_kh  [NBH*DH*WID];
__device__ int   g_topH[NBH*16];
__device__ int   g_topW[NBH*16];

// ---------------- channel layernorm (per pixel over 256 channels) ----------------
__global__ __launch_bounds__(256) void ln_kernel(const float* __restrict__ x,
                                                 const float* __restrict__ g,
                                                 const float* __restrict__ be,
                                                 float* __restrict__ out)
{
    int gp = blockIdx.x * 256 + threadIdx.x;           // 0..32767
    int b = gp >> 12, p = gp & 4095;
    const float* base = x + (long)b * CDIM * HW + p;
    float s = 0.f, s2 = 0.f;
    #pragma unroll 8
    for (int c = 0; c < CDIM; c++) { float v = base[(long)c * HW]; s += v; s2 += v * v; }
    float mean = s * (1.f / CDIM);
    float var  = s2 * (1.f / CDIM) - mean * mean;
    float inv  = rsqrtf(var + 1e-5f);
    float* ob = out + (long)b * CDIM * HW + p;
    #pragma unroll 8
    for (int c = 0; c < CDIM; c++) {
        float v = base[(long)c * HW];
        ob[(long)c * HW] = (v - mean) * inv * g[c] + be[c];
    }
}

// ---------------- TF32x3 tensor-core GEMM, fragment-packed + double-buffered --------
// C[z] = A(MxK) * B[z](KxN) (+bias)(+res).  A row-major shared across batch;
// B/C/res batched by stride.  M,N %128==0, K %16==0.
// 128x128 block tile, 8 warps (2x4), 64x32 warp tile, m16n8k8 tf32 mma.
// Smem holds tiles pre-packed in per-fragment lane layout:
//   A frag (16x8): uint4 per lane, stride 132 words / frag
//   B frag (8x8) : uint2 per lane, stride  66 words / frag
// Double-buffered stages (33792 B each); one __syncthreads per BK=16 iter.

__device__ __forceinline__ uint32_t f2tf(float x)
{
    uint32_t r;
    asm("cvt.rna.tf32.f32 %0, %1;" : "=r"(r) : "f"(x));
    return r;
}

#define MMA_TF32(c, a0, a1, a2, a3, b0, b1) \
    asm volatile("mma.sync.aligned.m16n8k8.row.col.f32.tf32.tf32.f32 " \
        "{%0,%1,%2,%3}, {%4,%5,%6,%7}, {%8,%9}, {%0,%1,%2,%3};" \
        : "+f"((c)[0]), "+f"((c)[1]), "+f"((c)[2]), "+f"((c)[3]) \
        : "r"(a0), "r"(a1), "r"(a2), "r"(a3), "r"(b0), "r"(b1))

#define AFRAG_STRIDE 132     // 128 words + pad
#define BFRAG_STRIDE 66      // 64 words + pad
#define STAGE_WORDS  (2*16*AFRAG_STRIDE + 2*32*BFRAG_STRIDE)   // 8448
#define TGEMM_SMEM   (2 * STAGE_WORDS * 4)                     // 67584 B

__global__ __launch_bounds__(256) void tgemm_kernel(
    const float* __restrict__ A, const float* __restrict__ B, float* __restrict__ C,
    int M, int N, int K, long strideB, long strideC,
    const float* __restrict__ bias, const float* __restrict__ res, long strideRes)
{
    extern __shared__ uint32_t sh[];
    int tid = threadIdx.x;
    int lane = tid & 31, warp = tid >> 5;
    int bx = blockIdx.x * 128, by = blockIdx.y * 128;
    const float* Bp = B + (long)blockIdx.z * strideB;
    float*       Cp = C + (long)blockIdx.z * strideC;

    float acc[4][4][4];
    #pragma unroll
    for (int i = 0; i < 4; i++)
        #pragma unroll
        for (int j = 0; j < 4; j++)
            #pragma unroll
            for (int k = 0; k < 4; k++) acc[i][j][k] = 0.f;

    // -------- staging addresses (per thread, slot-based) --------
    // A: slots s = tid, tid+256 -> frag f=s>>5, lane ls=s&31
    //    element block: m = (f>>1)*16 + (ls>>2), k = (f&1)*8 + (ls&3); gather 4
    // B: idx = tid, tid+256 -> k-row = idx>>5, n-quad = (idx&31)*4 (float4 coalesced)
    int sA0f = tid >> 5, sA0l = tid & 31;
    int sA1f = (tid + 256) >> 5, sA1l = tid & 31;
    long aOff0 = (long)(by + (sA0f >> 1) * 16 + (sA0l >> 2)) * K + (sA0f & 1) * 8 + (sA0l & 3);
    long aOff1 = (long)(by + (sA1f >> 1) * 16 + (sA1l >> 2)) * K + (sA1f & 1) * 8 + (sA1l & 3);
    int bK0 = tid >> 5, bN0 = (tid & 31) * 4;
    int bK1 = (tid + 256) >> 5, bN1 = (tid & 31) * 4;

    float pa[8];
    float4 pb[2];

    // prefetch tile 0
    {
        const float* ap0 = A + aOff0; const float* ap1 = A + aOff1;
        pa[0] = ap0[0]; pa[1] = ap0[8 * K]; pa[2] = ap0[4]; pa[3] = ap0[8 * K + 4];
        pa[4] = ap1[0]; pa[5] = ap1[8 * K]; pa[6] = ap1[4]; pa[7] = ap1[8 * K + 4];
        pb[0] = *(const float4*)(Bp + (long)bK0 * N + bx + bN0);
        pb[1] = *(const float4*)(Bp + (long)bK1 * N + bx + bN1);
    }

    int nIter = K >> 4;

    // stage tile 0 into buffer 0
    {
        uint32_t* AsB = sh;                    uint32_t* AsS = AsB + 16 * AFRAG_STRIDE;
        uint32_t* BsB = AsS + 16 * AFRAG_STRIDE; uint32_t* BsS = BsB + 32 * BFRAG_STRIDE;
        #pragma unroll
        for (int u = 0; u < 2; u++) {
            int f = u ? sA1f : sA0f, ls = u ? sA1l : sA0l;
            uint32_t bg[4], sm[4];
            #pragma unroll
            for (int j = 0; j < 4; j++) {
                float v = pa[u * 4 + j];
                bg[j] = f2tf(v); sm[j] = f2tf(v - __uint_as_float(bg[j]));
            }
            *(uint4*)&AsB[f * AFRAG_STRIDE + ls * 4] = make_uint4(bg[0], bg[1], bg[2], bg[3]);
            *(uint4*)&AsS[f * AFRAG_STRIDE + ls * 4] = make_uint4(sm[0], sm[1], sm[2], sm[3]);
            int kb = u ? bK1 : bK0, nb = u ? bN1 : bN0;
            float bv[4] = { pb[u].x, pb[u].y, pb[u].z, pb[u].w };
            #pragma unroll
            for (int j = 0; j < 4; j++) {
                int n = nb + j;
                int fB = (n >> 3) * 2 + (kb >> 3);
                int bl = ((n & 7) << 2) | (kb & 3);
                int rg = (kb >> 2) & 1;
                uint32_t big = f2tf(bv[j]);
                BsB[fB * BFRAG_STRIDE + bl * 2 + rg] = big;
                BsS[fB * BFRAG_STRIDE + bl * 2 + rg] = f2tf(bv[j] - __uint_as_float(big));
            }
        }
    }
    __syncthreads();

    int wmt = (warp >> 2) * 4;   // mtile base
    int wnt = (warp & 3) * 4;    // ntile base

    for (int it = 0; it < nIter; it++) {
        // prefetch next tile (LDG latency covered by MMA phase)
        if (it + 1 < nIter) {
            int k0 = (it + 1) << 4;
            const float* ap0 = A + aOff0 + k0; const float* ap1 = A + aOff1 + k0;
            pa[0] = ap0[0]; pa[1] = ap0[8 * K]; pa[2] = ap0[4]; pa[3] = ap0[8 * K + 4];
            pa[4] = ap1[0]; pa[5] = ap1[8 * K]; pa[6] = ap1[4]; pa[7] = ap1[8 * K + 4];
            pb[0] = *(const float4*)(Bp + (long)(k0 + bK0) * N + bx + bN0);
            pb[1] = *(const float4*)(Bp + (long)(k0 + bK1) * N + bx + bN1);
        }
        // compute on current buffer
        {
            uint32_t* base = sh + (it & 1) * STAGE_WORDS;
            const uint32_t* AsB = base;
            const uint32_t* AsS = AsB + 16 * AFRAG_STRIDE;
            const uint32_t* BsB = AsS + 16 * AFRAG_STRIDE;
            const uint32_t* BsS = BsB + 32 * BFRAG_STRIDE;
            #pragma unroll
            for (int ks = 0; ks < 2; ks++) {
                uint2 bB[4], bS[4];
                #pragma unroll
                for (int nt = 0; nt < 4; nt++) {
                    int fB = (wnt + nt) * 2 + ks;
                    bB[nt] = *(const uint2*)&BsB[fB * BFRAG_STRIDE + lane * 2];
                    bS[nt] = *(const uint2*)&BsS[fB * BFRAG_STRIDE + lane * 2];
                }
                #pragma unroll
                for (int mt = 0; mt < 4; mt++) {
                    int fA = (wmt + mt) * 2 + ks;
                    uint4 aB = *(const uint4*)&AsB[fA * AFRAG_STRIDE + lane * 4];
                    uint4 aS = *(const uint4*)&AsS[fA * AFRAG_STRIDE + lane * 4];
                    #pragma unroll
                    for (int nt = 0; nt < 4; nt++)
                        MMA_TF32(acc[mt][nt], aB.x, aB.y, aB.z, aB.w, bB[nt].x, bB[nt].y);
                    #pragma unroll
                    for (int nt = 0; nt < 4; nt++)
                        MMA_TF32(acc[mt][nt], aB.x, aB.y, aB.z, aB.w, bS[nt].x, bS[nt].y);
                    #pragma unroll
                    for (int nt = 0; nt < 4; nt++)
                        MMA_TF32(acc[mt][nt], aS.x, aS.y, aS.z, aS.w, bB[nt].x, bB[nt].y);
                }
            }
        }
        // stage next tile into alternate buffer
        if (it + 1 < nIter) {
            uint32_t* base = sh + ((it + 1) & 1) * STAGE_WORDS;
            uint32_t* AsB = base;                    uint32_t* AsS = AsB + 16 * AFRAG_STRIDE;
            uint32_t* BsB = AsS + 16 * AFRAG_STRIDE; uint32_t* BsS = BsB + 32 * BFRAG_STRIDE;
            #pragma unroll
            for (int u = 0; u < 2; u++) {
                int f = u ? sA1f : sA0f, ls = u ? sA1l : sA0l;
                uint32_t bg[4], sm[4];
                #pragma unroll
                for (int j = 0; j < 4; j++) {
                    float v = pa[u * 4 + j];
                    bg[j] = f2tf(v); sm[j] = f2tf(v - __uint_as_float(bg[j]));
                }
                *(uint4*)&AsB[f * AFRAG_STRIDE + ls * 4] = make_uint4(bg[0], bg[1], bg[2], bg[3]);
                *(uint4*)&AsS[f * AFRAG_STRIDE + ls * 4] = make_uint4(sm[0], sm[1], sm[2], sm[3]);
                int kb = u ? bK1 : bK0, nb = u ? bN1 : bN0;
                float bv[4] = { pb[u].x, pb[u].y, pb[u].z, pb[u].w };
                #pragma unroll
                for (int j = 0; j < 4; j++) {
                    int n = nb + j;
                    int fB = (n >> 3) * 2 + (kb >> 3);
                    int bl = ((n & 7) << 2) | (kb & 3);
                    int rg = (kb >> 2) & 1;
                    uint32_t big = f2tf(bv[j]);
                    BsB[fB * BFRAG_STRIDE + bl * 2 + rg] = big;
                    BsS[fB * BFRAG_STRIDE + bl * 2 + rg] = f2tf(bv[j] - __uint_as_float(big));
                }
            }
        }
        __syncthreads();
    }

    // epilogue
    int wm = (warp >> 2) * 64, wn = (warp & 3) * 32;
    int mr = lane >> 2, qc = (lane & 3) * 2;
    #pragma unroll
    for (int mt = 0; mt < 4; mt++) {
        int r0 = by + wm + mt * 16 + mr;
        float bb0 = bias ? bias[r0] : 0.f;
        float bb1 = bias ? bias[r0 + 8] : 0.f;
        #pragma unroll
        for (int nt = 0; nt < 4; nt++) {
            int c = bx + wn + nt * 8 + qc;
            long o0 = (long)r0 * N + c;
            long o1 = (long)(r0 + 8) * N + c;
            float2 v0 = make_float2(acc[mt][nt][0] + bb0, acc[mt][nt][1] + bb0);
            float2 v1 = make_float2(acc[mt][nt][2] + bb1, acc[mt][nt][3] + bb1);
            if (res) {
                const float* rp = res + (long)blockIdx.z * strideRes;
                v0.x += rp[o0]; v0.y += rp[o0 + 1];
                v1.x += rp[o1]; v1.y += rp[o1 + 1];
            }
            *(float2*)&Cp[o0] = v0;
            *(float2*)&Cp[o1] = v1;
        }
    }
}

// ---------------- l2-normalize q,k rows (along W=64) in place ----------------
__global__ __launch_bounds__(256) void l2norm_kernel(float* __restrict__ qkv)
{
    int gt = blockIdx.x * 256 + threadIdx.x;
    int warp = gt >> 5, lane = gt & 31;
    if (warp >= BD * 512 * WID) return;
    int b = warp / (512 * WID);
    int rem = warp % (512 * WID);
    float* p = qkv + (long)b * 768 * HW + (long)rem * WID;
    float v0 = p[lane], v1 = p[lane + 32];
    float s = v0 * v0 + v1 * v1;
    #pragma unroll
    for (int o = 16; o > 0; o >>= 1) s += __shfl_xor_sync(0xffffffffu, s, o);
    float scale = 1.f / fmaxf(sqrtf(s), 1e-12f);
    p[lane] = v0 * scale; p[lane + 32] = v1 * scale;
}

// ---------------- q_probe[bh][d] = sum over all pixels of normalized q ----------------
__global__ __launch_bounds__(256) void qprobe_kernel(const float* __restrict__ qkv,
                                                     float* __restrict__ qp)
{
    __shared__ float sm[8];
    int c = blockIdx.x;                     // 0..2047 = bh*32+d
    int bh = c >> 5, d = c & 31, b = bh >> 3, hh = bh & 7;
    const float* p = qkv + (long)b * 768 * HW + (long)(hh * 32 + d) * HW;
    float s = 0.f;
    for (int i = threadIdx.x; i < HW; i += 256) s += p[i];
    #pragma unroll
    for (int o = 16; o > 0; o >>= 1) s += __shfl_xor_sync(0xffffffffu, s, o);
    if ((threadIdx.x & 31) == 0) sm[threadIdx.x >> 5] = s;
    __syncthreads();
    if (threadIdx.x == 0) { float t = 0; for (int i = 0; i < 8; i++) t += sm[i]; qp[c] = t; }
}

// ---------------- k_height[bh][d][h] = sum over w of normalized k ----------------
__global__ __launch_bounds__(256) void kheight_kernel(const float* __restrict__ qkv,
                                                      float* __restrict__ kh)
{
    int gt = blockIdx.x * 256 + threadIdx.x;
    int warp = gt >> 5, lane = gt & 31;
    if (warp >= NBH * DH * WID) return;
    int h = warp & 63; int rest = warp >> 6; int d = rest & 31; int bh = rest >> 5;
    int b = bh >> 3, hh = bh & 7;
    const float* p = qkv + (long)b * 768 * HW + (long)(256 + hh * 32 + d) * HW + h * WID;
    float s = p[lane] + p[lane + 32];
    #pragma unroll
    for (int o = 16; o > 0; o >>= 1) s += __shfl_xor_sync(0xffffffffu, s, o);
    if (lane == 0) kh[warp] = s;
}

// ---------------- score_r + top-16 rows (set only; order irrelevant downstream) ---------
__global__ void toph_kernel(const float* __restrict__ qp, const float* __restrict__ kh,
                            int* __restrict__ topH)
{
    __shared__ float sc[64]; __shared__ float qs[32];
    int bh = blockIdx.x, t = threadIdx.x;                  // 64 threads
    if (t < 32) qs[t] = qp[bh * 32 + t];
    __syncthreads();
    float s = 0.f;
    #pragma unroll
    for (int d = 0; d < 32; d++) s += qs[d] * kh[((bh * 32 + d) << 6) + t];
    sc[t] = s;
    __syncthreads();
    if (t == 0) {
        for (int it = 0; it < 16; it++) {
            float best = -3.4e38f; int bi = 0;
            for (int h = 0; h < 64; h++) if (sc[h] > best) { best = sc[h]; bi = h; }
            topH[bh * 16 + it] = bi; sc[bi] = -3.4e38f;
        }
    }
}

// ---------------- gather selected rows of k,v -> kg/vg [bh][d][16][64] -----------------
__global__ __launch_bounds__(256) void gather_rows_kernel(const float* __restrict__ qkv,
                                                          const int* __restrict__ topH,
                                                          float* __restrict__ kg,
                                                          float* __restrict__ vg)
{
    long i = (long)blockIdx.x * 256 + threadIdx.x;          // 64*32*16*64
    int w = i & 63; long r = i >> 6; int t = (int)(r & 15); r >>= 4;
    int d = (int)(r & 31); int bh = (int)(r >> 5);
    int b = bh >> 3, hh = bh & 7;
    int h = topH[bh * 16 + t];
    long base = (long)b * 768 * HW + (long)(hh * 32 + d) * HW + (long)h * WID + w;
    kg[i] = qkv[base + 256L * HW];
    vg[i] = qkv[base + 512L * HW];
}

// ---------------- score_c + top-16 columns ----------------
__global__ void topw_kernel(const float* __restrict__ qp, const float* __restrict__ kg,
                            int* __restrict__ topW)
{
    __shared__ float sc[64]; __shared__ float qs[32];
    int bh = blockIdx.x, t = threadIdx.x;                  // t = w, 64 threads
    if (t < 32) qs[t] = qp[bh * 32 + t];
    __syncthreads();
    float s = 0.f;
    for (int d = 0; d < 32; d++) {
        float colsum = 0.f;
        #pragma unroll
        for (int i = 0; i < 16; i++)
            colsum += kg[(((long)(bh * 32 + d) * 16) + i) * 64 + t];
        s += qs[d] * colsum;
    }
    sc[t] = s;
    __syncthreads();
    if (t == 0) {
        for (int it = 0; it < 16; it++) {
            float best = -3.4e38f; int bi = 0;
            for (int w = 0; w < 64; w++) if (sc[w] > best) { best = sc[w]; bi = w; }
            topW[bh * 16 + it] = bi; sc[bi] = -3.4e38f;
        }
    }
}

// ---------------- build kf/vf [bh][j][d], j = i*16 + jw ----------------
__global__ __launch_bounds__(256) void build_kv_kernel(const float* __restrict__ kg,
                                                       const float* __restrict__ vg,
                                                       const int* __restrict__ topW,
                                                       float* __restrict__ kf,
                                                       float* __restrict__ vf)
{
    long i = (long)blockIdx.x * 256 + threadIdx.x;          // 64*256*32
    int d = (int)(i & 31); long r = i >> 5; int j = (int)(r & 255); int bh = (int)(r >> 8);
    int ti = j >> 4, jw = j & 15;
    int w = topW[bh * 16 + jw];
    long src = (((long)(bh * 32 + d) * 16) + ti) * 64 + w;
    kf[i] = kg[src]; vf[i] = vg[src];
}

// ---------------- fused sparse attention: softmax(Q Kf^T) Vf ----------------
__global__ __launch_bounds__(128) void attn_kernel(const float* __restrict__ qkv,
                                                   const float* __restrict__ kf,
                                                   const float* __restrict__ vf,
                                                   float* __restrict__ out)
{
    __shared__ float kfs[128 * 32];
    __shared__ float vfs[128 * 32];
    int bh = blockIdx.y;
    int b = bh >> 3, hh = bh & 7;
    int p = blockIdx.x * 128 + threadIdx.x;
    const float* qb = qkv + (long)b * 768 * HW + (long)(hh * 32) * HW + p;
    float q[32], acc[32];
    #pragma unroll
    for (int d = 0; d < 32; d++) { q[d] = qb[(long)d * HW]; acc[d] = 0.f; }
    float l = 0.f;
    for (int ch = 0; ch < 2; ch++) {
        const float4* kc = (const float4*)(kf + ((long)bh * NKEY + ch * 128) * 32);
        const float4* vc = (const float4*)(vf + ((long)bh * NKEY + ch * 128) * 32);
        for (int i = threadIdx.x; i < 1024; i += 128) {
            ((float4*)kfs)[i] = kc[i];
            ((float4*)vfs)[i] = vc[i];
        }
        __syncthreads();
        for (int j = 0; j < 128; j++) {
            const float4* k4 = (const float4*)&kfs[j * 32];
            float s = 0.f;
            #pragma unroll
            for (int d4 = 0; d4 < 8; d4++) {
                float4 kk = k4[d4];
                s += q[d4 * 4 + 0] * kk.x + q[d4 * 4 + 1] * kk.y
                   + q[d4 * 4 + 2] * kk.z + q[d4 * 4 + 3] * kk.w;
            }
            float e = __expf(s);
            l += e;
            const float4* v4 = (const float4*)&vfs[j * 32];
            #pragma unroll
            for (int d4 = 0; d4 < 8; d4++) {
                float4 vv = v4[d4];
                acc[d4 * 4 + 0] = fmaf(e, vv.x, acc[d4 * 4 + 0]);
                acc[d4 * 4 + 1] = fmaf(e, vv.y, acc[d4 * 4 + 1]);
                acc[d4 * 4 + 2] = fmaf(e, vv.z, acc[d4 * 4 + 2]);
                acc[d4 * 4 + 3] = fmaf(e, vv.w, acc[d4 * 4 + 3]);
            }
        }
        __syncthreads();
    }
    float inv = 1.f / l;
    float* ob = out + (long)b * CDIM * HW + (long)(hh * 32) * HW + p;
    #pragma unroll
    for (int d = 0; d < 32; d++) ob[(long)d * HW] = acc[d] * inv;
}

// ---------------- depthwise 3x3 SAME ----------------
__global__ __launch_bounds__(256) void dwconv_kernel(const float* __restrict__ in,
                                                     const float* __restrict__ w,
                                                     const float* __restrict__ bias,
                                                     float* __restrict__ out,
                                                     int C, long inBS, long outBS, int chanOff)
{
    int idx = blockIdx.x;
    int yt = idx & 15; idx >>= 4;
    int c = idx % C; int b = idx / C;
    int x = threadIdx.x & 63;
    int y = yt * 4 + (threadIdx.x >> 6);
    const float* ip = in + (long)b * inBS + (long)c * HW;
    const float* wp = w + c * 9;
    float s = bias[c];
    #pragma unroll
    for (int dy = 0; dy < 3; dy++) {
        int yy = y + dy - 1;
        if (yy < 0 || yy > 63) continue;
        #pragma unroll
        for (int dx = 0; dx < 3; dx++) {
            int xx = x + dx - 1;
            if (xx < 0 || xx > 63) continue;
            s += wp[dy * 3 + dx] * ip[yy * 64 + xx];
        }
    }
    out[(long)b * outBS + (long)(chanOff + c) * HW + y * 64 + x] = s;
}

// ---------------- instance norm (+gelu)(+add) ----------------
__device__ __forceinline__ float gelu_exact(float u)
{
    return 0.5f * u * (1.f + erff(u * 0.7071067811865476f));
}

template <int MODE>  // 0: norm; 1: gelu(norm); 2: add + gelu(norm)
__global__ __launch_bounds__(256) void instnorm_kernel(const float* __restrict__ in,
                                                       const float* __restrict__ addsrc,
                                                       float* __restrict__ out)
{
    __shared__ float sm[16];
    long row = blockIdx.x;
    const float4* p = (const float4*)(in + row * HW);
    int t = threadIdx.x;
    float4 v[4];
    float s = 0.f, s2 = 0.f;
    #pragma unroll
    for (int i = 0; i < 4; i++) {
        v[i] = p[t + i * 256];
        s  += v[i].x + v[i].y + v[i].z + v[i].w;
        s2 += v[i].x * v[i].x + v[i].y * v[i].y + v[i].z * v[i].z + v[i].w * v[i].w;
    }
    #pragma unroll
    for (int o = 16; o > 0; o >>= 1) {
        s  += __shfl_xor_sync(0xffffffffu, s, o);
        s2 += __shfl_xor_sync(0xffffffffu, s2, o);
    }
    if ((t & 31) == 0) { sm[t >> 5] = s; sm[8 + (t >> 5)] = s2; }
    __syncthreads();
    if (t == 0) {
        float a = 0.f, b2 = 0.f;
        for (int i = 0; i < 8; i++) { a += sm[i]; b2 += sm[8 + i]; }
        sm[0] = a; sm[8] = b2;
    }
    __syncthreads();
    float mean = sm[0] * (1.f / HW);
    float var  = sm[8] * (1.f / HW) - mean * mean;
    float inv  = rsqrtf(var + 1e-5f);
    float4* op = (float4*)(out + row * HW);
    const float4* ap = (MODE == 2) ? (const float4*)(addsrc + row * HW) : nullptr;
    #pragma unroll
    for (int i = 0; i < 4; i++) {
        float4 u = v[i];
        u.x = (u.x - mean) * inv; u.y = (u.y - mean) * inv;
        u.z = (u.z - mean) * inv; u.w = (u.w - mean) * inv;
        if (MODE >= 1) {
            u.x = gelu_exact(u.x); u.y = gelu_exact(u.y);
            u.z = gelu_exact(u.z); u.w = gelu_exact(u.w);
        }
        if (MODE == 2) {
            float4 a = ap[t + i * 256];
            u.x += a.x; u.y += a.y; u.z += a.z; u.w += a.w;
        }
        op[t + i * 256] = u;
    }
}

// ---------------- host launcher ----------------
extern "C" void kernel_launch(void* const* d_in, const int* in_sizes, int n_in,
                              void* d_out, int out_size)
{
    (void)in_sizes; (void)n_in; (void)out_size;
    const float* x      = (const float*)d_in[0];
    const float* ln_g   = (const float*)d_in[1];
    const float* ln_b   = (const float*)d_in[2];
    const float* w_qkv  = (const float*)d_in[3];
    const float* w_out  = (const float*)d_in[4];
    const float* b_out  = (const float*)d_in[5];
    const float* w_dw   = (const float*)d_in[6];
    const float* b_dw   = (const float*)d_in[7];
    const float* w_comb = (const float*)d_in[8];
    const float* b_comb = (const float*)d_in[9];
    const float* w_ff1  = (const float*)d_in[10];
    const float* b_ff1  = (const float*)d_in[11];
    const float* w_ffdw = (const float*)d_in[12];
    const float* b_ffdw = (const float*)d_in[13];
    const float* w_ff2  = (const float*)d_in[14];
    const float* b_ff2  = (const float*)d_in[15];
    float* out = (float*)d_out;

    void *p;
    cudaGetSymbolAddress(&p, g_xn);   float* xn   = (float*)p;
    cudaGetSymbolAddress(&p, g_qkv);  float* qkv  = (float*)p;
    cudaGetSymbolAddress(&p, g_attn); float* attn = (float*)p;
    cudaGetSymbolAddress(&p, g_cat);  float* cat  = (float*)p;
    cudaGetSymbolAddress(&p, g_ao);   float* ao   = (float*)p;
    cudaGetSymbolAddress(&p, g_h);    float* h    = (float*)p;
    cudaGetSymbolAddress(&p, g_hg);   float* hg   = (float*)p;
    cudaGetSymbolAddress(&p, g_dwb);  float* dwb  = (float*)p;
    cudaGetSymbolAddress(&p, g_kg);   float* kg   = (float*)p;
    cudaGetSymbolAddress(&p, g_vg);   float* vg   = (float*)p;
    cudaGetSymbolAddress(&p, g_kf);   float* kf   = (float*)p;
    cudaGetSymbolAddress(&p, g_vf);   float* vf   = (float*)p;
    cudaGetSymbolAddress(&p, g_qp);   float* qp   = (float*)p;
    cudaGetSymbolAddress(&p, g_kh);   float* kh   = (float*)p;
    cudaGetSymbolAddress(&p, g_topH); int*   topH = (int*)p;
    cudaGetSymbolAddress(&p, g_topW); int*   topW = (int*)p;

    // allow 66 KB dynamic smem for the GEMM (non-stream call; capture-safe)
    cudaFuncSetAttribute(tgemm_kernel, cudaFuncAttributeMaxDynamicSharedMemorySize,
                         TGEMM_SMEM);

    // 1. channel layernorm
    ln_kernel<<<128, 256>>>(x, ln_g, ln_b, xn);
    // 2. qkv projection (768x256 @ 256x4096, per batch)
    tgemm_kernel<<<dim3(32, 6, BD), 256, TGEMM_SMEM>>>(w_qkv, xn, qkv, 768, HW, 256,
                                           (long)CDIM * HW, (long)768 * HW,
                                           nullptr, nullptr, 0);
    // 3. l2-normalize q,k along W (in place)
    l2norm_kernel<<<32768, 256>>>(qkv);
    // 4. probes + top-k selection
    qprobe_kernel<<<2048, 256>>>(qkv, qp);
    kheight_kernel<<<16384, 256>>>(qkv, kh);
    toph_kernel<<<64, 64>>>(qp, kh, topH);
    gather_rows_kernel<<<8192, 256>>>(qkv, topH, kg, vg);
    topw_kernel<<<64, 64>>>(qp, kg, topW);
    build_kv_kernel<<<2048, 256>>>(kg, vg, topW, kf, vf);
    // 5. fused sparse attention
    attn_kernel<<<dim3(32, NBH), 128>>>(qkv, kf, vf, attn);
    // 6. out-proj into concat buffer rows [0,256)
    tgemm_kernel<<<dim3(32, 2, BD), 256, TGEMM_SMEM>>>(w_out, attn, cat, 256, HW, 256,
                                           (long)CDIM * HW, (long)512 * HW,
                                           b_out, nullptr, 0);
    // 7. dwconv branch into concat buffer rows [256,512)
    dwconv_kernel<<<BD * 256 * 16, 256>>>(x, w_dw, b_dw, cat, 256,
                                          (long)CDIM * HW, (long)512 * HW, 256);
    // 8. combine (K=512) + bias + residual x
    tgemm_kernel<<<dim3(32, 2, BD), 256, TGEMM_SMEM>>>(w_comb, cat, ao, 256, HW, 512,
                                           (long)512 * HW, (long)CDIM * HW,
                                           b_comb, x, (long)CDIM * HW);
    // 9. ff1
    tgemm_kernel<<<dim3(32, 8, BD), 256, TGEMM_SMEM>>>(w_ff1, ao, h, FFI, HW, 256,
                                           (long)CDIM * HW, (long)FFI * HW,
                                           b_ff1, nullptr, 0);
    // 10. h = gelu(instnorm(h))
    instnorm_kernel<1><<<BD * FFI, 256>>>(h, nullptr, hg);
    // 11. dwconv(ffdw)
    dwconv_kernel<<<BD * FFI * 16, 256>>>(hg, w_ffdw, b_ffdw, dwb, FFI,
                                          (long)FFI * HW, (long)FFI * HW, 0);
    // 12. h = hg + gelu(instnorm(dw))
    instnorm_kernel<2><<<BD * FFI, 256>>>(dwb, hg, h);
    // 13. ff2 (reuse xn buffer for output)
    tgemm_kernel<<<dim3(32, 2, BD), 256, TGEMM_SMEM>>>(w_ff2, h, xn, 256, HW, 1024,
                                           (long)FFI * HW, (long)CDIM * HW,
                                           b_ff2, nullptr, 0);
    // 14. final instance norm -> d_out
    instnorm_kernel<0><<<BD * CDIM, 256>>>(xn, nullptr, out);
}

// round 10
// speedup vs baseline: 1.2885x; 1.0004x over previous
#include <cuda_runtime.h>
#include <math.h>
#include <stdint.h>

// ---------------- problem constants ----------------
#define BD     8          // batch
#define HEADS  8
#define DH     32         // dim head
#define CDIM   256        // model dim
#define FFI    1024       // ff inner
#define HW     4096       // 64*64 pixels
#define WID    64
#define NBH    64         // BD*HEADS
#define NKEY   256        // TOP_H * TOP_W

// ---------------- scratch (device globals: no allocs allowed) ----------------
__device__ float g_xn  [(long)BD*CDIM*HW];   // LN(x); reused for ff2 output
__device__ float g_qkv [(long)BD*768*HW];
__device__ float g_attn[(long)BD*CDIM*HW];
__device__ float g_cat [(long)BD*512*HW];
__device__ float g_ao  [(long)BD*CDIM*HW];
__device__ float g_h   [(long)BD*FFI*HW];
__device__ float g_hg  [(long)BD*FFI*HW];
__device__ float g_dwb [(long)BD*FFI*HW];
__device__ float g_kg  [NBH*DH*16*WID];
__device__ float g_vg  [NBH*DH*16*WID];
__device__ float g_kf  [NBH*NKEY*DH];
__device__ float g_vf  [NBH*NKEY*DH];
__device__ float g_qp  [NBH*DH];
__device__ float g_kh  [NBH*DH*WID];
__device__ int   g_topH[NBH*16];
__device__ int   g_topW[NBH*16];

// ---------------- channel layernorm (per pixel over 256 channels) ----------------
__global__ __launch_bounds__(256) void ln_kernel(const float* __restrict__ x,
                                                 const float* __restrict__ g,
                                                 const float* __restrict__ be,
                                                 float* __restrict__ out)
{
    int gp = blockIdx.x * 256 + threadIdx.x;           // 0..32767
    int b = gp >> 12, p = gp & 4095;
    const float* base = x + (long)b * CDIM * HW + p;
    float s = 0.f, s2 = 0.f;
    #pragma unroll 8
    for (int c = 0; c < CDIM; c++) { float v = base[(long)c * HW]; s += v; s2 += v * v; }
    float mean = s * (1.f / CDIM);
    float var  = s2 * (1.f / CDIM) - mean * mean;
    float inv  = rsqrtf(var + 1e-5f);
    float* ob = out + (long)b * CDIM * HW + p;
    #pragma unroll 8
    for (int c = 0; c < CDIM; c++) {
        float v = base[(long)c * HW];
        ob[(long)c * HW] = (v - mean) * inv * g[c] + be[c];
    }
}

// ---------------- TF32x3 tensor-core GEMM, fragment-packed + double-buffered --------
// C[z] = A(MxK) * B[z](KxN) (+bias)(+res).  A row-major shared across batch;
// B/C/res batched by stride.  M,N %128==0, K %16==0.
// 128x128 block tile, 8 warps (2x4), 64x32 warp tile, m16n8k8 tf32 mma.
// Smem holds tiles pre-packed in per-fragment lane layout:
//   A frag (16x8): uint4 per lane, stride 132 words / frag
//   B frag (8x8) : uint2 per lane, stride  66 words / frag
// Double-buffered stages (33792 B each); one __syncthreads per BK=16 iter.

__device__ __forceinline__ uint32_t f2tf(float x)
{
    uint32_t r;
    asm("cvt.rna.tf32.f32 %0, %1;" : "=r"(r) : "f"(x));
    return r;
}

#define MMA_TF32(c, a0, a1, a2, a3, b0, b1) \
    asm volatile("mma.sync.aligned.m16n8k8.row.col.f32.tf32.tf32.f32 " \
        "{%0,%1,%2,%3}, {%4,%5,%6,%7}, {%8,%9}, {%0,%1,%2,%3};" \
        : "+f"((c)[0]), "+f"((c)[1]), "+f"((c)[2]), "+f"((c)[3]) \
        : "r"(a0), "r"(a1), "r"(a2), "r"(a3), "r"(b0), "r"(b1))

#define AFRAG_STRIDE 132     // 128 words + pad
#define BFRAG_STRIDE 66      // 64 words + pad
#define STAGE_WORDS  (2*16*AFRAG_STRIDE + 2*32*BFRAG_STRIDE)   // 8448
#define TGEMM_SMEM   (2 * STAGE_WORDS * 4)                     // 67584 B

__global__ __launch_bounds__(256) void tgemm_kernel(
    const float* __restrict__ A, const float* __restrict__ B, float* __restrict__ C,
    int M, int N, int K, long strideB, long strideC,
    const float* __restrict__ bias, const float* __restrict__ res, long strideRes)
{
    extern __shared__ uint32_t sh[];
    int tid = threadIdx.x;
    int lane = tid & 31, warp = tid >> 5;
    int bx = blockIdx.x * 128, by = blockIdx.y * 128;
    const float* Bp = B + (long)blockIdx.z * strideB;
    float*       Cp = C + (long)blockIdx.z * strideC;

    float acc[4][4][4];
    #pragma unroll
    for (int i = 0; i < 4; i++)
        #pragma unroll
        for (int j = 0; j < 4; j++)
            #pragma unroll
            for (int k = 0; k < 4; k++) acc[i][j][k] = 0.f;

    // -------- staging addresses (per thread, slot-based) --------
    // A: slots s = tid, tid+256 -> frag f=s>>5, lane ls=s&31
    //    element block: m = (f>>1)*16 + (ls>>2), k = (f&1)*8 + (ls&3); gather 4
    // B: idx = tid, tid+256 -> k-row = idx>>5, n-quad = (idx&31)*4 (float4 coalesced)
    int sA0f = tid >> 5, sA0l = tid & 31;
    int sA1f = (tid + 256) >> 5, sA1l = tid & 31;
    long aOff0 = (long)(by + (sA0f >> 1) * 16 + (sA0l >> 2)) * K + (sA0f & 1) * 8 + (sA0l & 3);
    long aOff1 = (long)(by + (sA1f >> 1) * 16 + (sA1l >> 2)) * K + (sA1f & 1) * 8 + (sA1l & 3);
    int bK0 = tid >> 5, bN0 = (tid & 31) * 4;
    int bK1 = (tid + 256) >> 5, bN1 = (tid & 31) * 4;

    float pa[8];
    float4 pb[2];

    // prefetch tile 0
    {
        const float* ap0 = A + aOff0; const float* ap1 = A + aOff1;
        pa[0] = ap0[0]; pa[1] = ap0[8 * K]; pa[2] = ap0[4]; pa[3] = ap0[8 * K + 4];
        pa[4] = ap1[0]; pa[5] = ap1[8 * K]; pa[6] = ap1[4]; pa[7] = ap1[8 * K + 4];
        pb[0] = *(const float4*)(Bp + (long)bK0 * N + bx + bN0);
        pb[1] = *(const float4*)(Bp + (long)bK1 * N + bx + bN1);
    }

    int nIter = K >> 4;

    // stage tile 0 into buffer 0
    {
        uint32_t* AsB = sh;                    uint32_t* AsS = AsB + 16 * AFRAG_STRIDE;
        uint32_t* BsB = AsS + 16 * AFRAG_STRIDE; uint32_t* BsS = BsB + 32 * BFRAG_STRIDE;
        #pragma unroll
        for (int u = 0; u < 2; u++) {
            int f = u ? sA1f : sA0f, ls = u ? sA1l : sA0l;
            uint32_t bg[4], sm[4];
            #pragma unroll
            for (int j = 0; j < 4; j++) {
                float v = pa[u * 4 + j];
                bg[j] = f2tf(v); sm[j] = f2tf(v - __uint_as_float(bg[j]));
            }
            *(uint4*)&AsB[f * AFRAG_STRIDE + ls * 4] = make_uint4(bg[0], bg[1], bg[2], bg[3]);
            *(uint4*)&AsS[f * AFRAG_STRIDE + ls * 4] = make_uint4(sm[0], sm[1], sm[2], sm[3]);
            int kb = u ? bK1 : bK0, nb = u ? bN1 : bN0;
            float bv[4] = { pb[u].x, pb[u].y, pb[u].z, pb[u].w };
            #pragma unroll
            for (int j = 0; j < 4; j++) {
                int n = nb + j;
                int fB = (n >> 3) * 2 + (kb >> 3);
                int bl = ((n & 7) << 2) | (kb & 3);
                int rg = (kb >> 2) & 1;
                uint32_t big = f2tf(bv[j]);
                BsB[fB * BFRAG_STRIDE + bl * 2 + rg] = big;
                BsS[fB * BFRAG_STRIDE + bl * 2 + rg] = f2tf(bv[j] - __uint_as_float(big));
            }
        }
    }
    __syncthreads();

    int wmt = (warp >> 2) * 4;   // mtile base
    int wnt = (warp & 3) * 4;    // ntile base

    for (int it = 0; it < nIter; it++) {
        // prefetch next tile (LDG latency covered by MMA phase)
        if (it + 1 < nIter) {
            int k0 = (it + 1) << 4;
            const float* ap0 = A + aOff0 + k0; const float* ap1 = A + aOff1 + k0;
            pa[0] = ap0[0]; pa[1] = ap0[8 * K]; pa[2] = ap0[4]; pa[3] = ap0[8 * K + 4];
            pa[4] = ap1[0]; pa[5] = ap1[8 * K]; pa[6] = ap1[4]; pa[7] = ap1[8 * K + 4];
            pb[0] = *(const float4*)(Bp + (long)(k0 + bK0) * N + bx + bN0);
            pb[1] = *(const float4*)(Bp + (long)(k0 + bK1) * N + bx + bN1);
        }
        // compute on current buffer
        {
            uint32_t* base = sh + (it & 1) * STAGE_WORDS;
            const uint32_t* AsB = base;
            const uint32_t* AsS = AsB + 16 * AFRAG_STRIDE;
            const uint32_t* BsB = AsS + 16 * AFRAG_STRIDE;
            const uint32_t* BsS = BsB + 32 * BFRAG_STRIDE;
            #pragma unroll
            for (int ks = 0; ks < 2; ks++) {
                uint2 bB[4], bS[4];
                #pragma unroll
                for (int nt = 0; nt < 4; nt++) {
                    int fB = (wnt + nt) * 2 + ks;
                    bB[nt] = *(const uint2*)&BsB[fB * BFRAG_STRIDE + lane * 2];
                    bS[nt] = *(const uint2*)&BsS[fB * BFRAG_STRIDE + lane * 2];
                }
                #pragma unroll
                for (int mt = 0; mt < 4; mt++) {
                    int fA = (wmt + mt) * 2 + ks;
                    uint4 aB = *(const uint4*)&AsB[fA * AFRAG_STRIDE + lane * 4];
                    uint4 aS = *(const uint4*)&AsS[fA * AFRAG_STRIDE + lane * 4];
                    #pragma unroll
                    for (int nt = 0; nt < 4; nt++)
                        MMA_TF32(acc[mt][nt], aB.x, aB.y, aB.z, aB.w, bB[nt].x, bB[nt].y);
                    #pragma unroll
                    for (int nt = 0; nt < 4; nt++)
                        MMA_TF32(acc[mt][nt], aB.x, aB.y, aB.z, aB.w, bS[nt].x, bS[nt].y);
                    #pragma unroll
                    for (int nt = 0; nt < 4; nt++)
                        MMA_TF32(acc[mt][nt], aS.x, aS.y, aS.z, aS.w, bB[nt].x, bB[nt].y);
                }
            }
        }
        // stage next tile into alternate buffer
        if (it + 1 < nIter) {
            uint32_t* base = sh + ((it + 1) & 1) * STAGE_WORDS;
            uint32_t* AsB = base;                    uint32_t* AsS = AsB + 16 * AFRAG_STRIDE;
            uint32_t* BsB = AsS + 16 * AFRAG_STRIDE; uint32_t* BsS = BsB + 32 * BFRAG_STRIDE;
            #pragma unroll
            for (int u = 0; u < 2; u++) {
                int f = u ? sA1f : sA0f, ls = u ? sA1l : sA0l;
                uint32_t bg[4], sm[4];
                #pragma unroll
                for (int j = 0; j < 4; j++) {
                    float v = pa[u * 4 + j];
                    bg[j] = f2tf(v); sm[j] = f2tf(v - __uint_as_float(bg[j]));
                }
                *(uint4*)&AsB[f * AFRAG_STRIDE + ls * 4] = make_uint4(bg[0], bg[1], bg[2], bg[3]);
                *(uint4*)&AsS[f * AFRAG_STRIDE + ls * 4] = make_uint4(sm[0], sm[1], sm[2], sm[3]);
                int kb = u ? bK1 : bK0, nb = u ? bN1 : bN0;
                float bv[4] = { pb[u].x, pb[u].y, pb[u].z, pb[u].w };
                #pragma unroll
                for (int j = 0; j < 4; j++) {
                    int n = nb + j;
                    int fB = (n >> 3) * 2 + (kb >> 3);
                    int bl = ((n & 7) << 2) | (kb & 3);
                    int rg = (kb >> 2) & 1;
                    uint32_t big = f2tf(bv[j]);
                    BsB[fB * BFRAG_STRIDE + bl * 2 + rg] = big;
                    BsS[fB * BFRAG_STRIDE + bl * 2 + rg] = f2tf(bv[j] - __uint_as_float(big));
                }
            }
        }
        __syncthreads();
    }

    // epilogue
    int wm = (warp >> 2) * 64, wn = (warp & 3) * 32;
    int mr = lane >> 2, qc = (lane & 3) * 2;
    #pragma unroll
    for (int mt = 0; mt < 4; mt++) {
        int r0 = by + wm + mt * 16 + mr;
        float bb0 = bias ? bias[r0] : 0.f;
        float bb1 = bias ? bias[r0 + 8] : 0.f;
        #pragma unroll
        for (int nt = 0; nt < 4; nt++) {
            int c = bx + wn + nt * 8 + qc;
            long o0 = (long)r0 * N + c;
            long o1 = (long)(r0 + 8) * N + c;
            float2 v0 = make_float2(acc[mt][nt][0] + bb0, acc[mt][nt][1] + bb0);
            float2 v1 = make_float2(acc[mt][nt][2] + bb1, acc[mt][nt][3] + bb1);
            if (res) {
                const float* rp = res + (long)blockIdx.z * strideRes;
                v0.x += rp[o0]; v0.y += rp[o0 + 1];
                v1.x += rp[o1]; v1.y += rp[o1 + 1];
            }
            *(float2*)&Cp[o0] = v0;
            *(float2*)&Cp[o1] = v1;
        }
    }
}

// ---------------- l2-normalize q,k rows (along W=64) in place ----------------
__global__ __launch_bounds__(256) void l2norm_kernel(float* __restrict__ qkv)
{
    int gt = blockIdx.x * 256 + threadIdx.x;
    int warp = gt >> 5, lane = gt & 31;
    if (warp >= BD * 512 * WID) return;
    int b = warp / (512 * WID);
    int rem = warp % (512 * WID);
    float* p = qkv + (long)b * 768 * HW + (long)rem * WID;
    float v0 = p[lane], v1 = p[lane + 32];
    float s = v0 * v0 + v1 * v1;
    #pragma unroll
    for (int o = 16; o > 0; o >>= 1) s += __shfl_xor_sync(0xffffffffu, s, o);
    float scale = 1.f / fmaxf(sqrtf(s), 1e-12f);
    p[lane] = v0 * scale; p[lane + 32] = v1 * scale;
}

// ---------------- q_probe[bh][d] = sum over all pixels of normalized q ----------------
__global__ __launch_bounds__(256) void qprobe_kernel(const float* __restrict__ qkv,
                                                     float* __restrict__ qp)
{
    __shared__ float sm[8];
    int c = blockIdx.x;                     // 0..2047 = bh*32+d
    int bh = c >> 5, d = c & 31, b = bh >> 3, hh = bh & 7;
    const float* p = qkv + (long)b * 768 * HW + (long)(hh * 32 + d) * HW;
    float s = 0.f;
    for (int i = threadIdx.x; i < HW; i += 256) s += p[i];
    #pragma unroll
    for (int o = 16; o > 0; o >>= 1) s += __shfl_xor_sync(0xffffffffu, s, o);
    if ((threadIdx.x & 31) == 0) sm[threadIdx.x >> 5] = s;
    __syncthreads();
    if (threadIdx.x == 0) { float t = 0; for (int i = 0; i < 8; i++) t += sm[i]; qp[c] = t; }
}

// ---------------- k_height[bh][d][h] = sum over w of normalized k ----------------
__global__ __launch_bounds__(256) void kheight_kernel(const float* __restrict__ qkv,
                                                      float* __restrict__ kh)
{
    int gt = blockIdx.x * 256 + threadIdx.x;
    int warp = gt >> 5, lane = gt & 31;
    if (warp >= NBH * DH * WID) return;
    int h = warp & 63; int rest = warp >> 6; int d = rest & 31; int bh = rest >> 5;
    int b = bh >> 3, hh = bh & 7;
    const float* p = qkv + (long)b * 768 * HW + (long)(256 + hh * 32 + d) * HW + h * WID;
    float s = p[lane] + p[lane + 32];
    #pragma unroll
    for (int o = 16; o > 0; o >>= 1) s += __shfl_xor_sync(0xffffffffu, s, o);
    if (lane == 0) kh[warp] = s;
}

// ---------------- score_r + top-16 rows (set only; order irrelevant downstream) ---------
__global__ void toph_kernel(const float* __restrict__ qp, const float* __restrict__ kh,
                            int* __restrict__ topH)
{
    __shared__ float sc[64]; __shared__ float qs[32];
    int bh = blockIdx.x, t = threadIdx.x;                  // 64 threads
    if (t < 32) qs[t] = qp[bh * 32 + t];
    __syncthreads();
    float s = 0.f;
    #pragma unroll
    for (int d = 0; d < 32; d++) s += qs[d] * kh[((bh * 32 + d) << 6) + t];
    sc[t] = s;
    __syncthreads();
    if (t == 0) {
        for (int it = 0; it < 16; it++) {
            float best = -3.4e38f; int bi = 0;
            for (int h = 0; h < 64; h++) if (sc[h] > best) { best = sc[h]; bi = h; }
            topH[bh * 16 + it] = bi; sc[bi] = -3.4e38f;
        }
    }
}

// ---------------- gather selected rows of k,v -> kg/vg [bh][d][16][64] -----------------
__global__ __launch_bounds__(256) void gather_rows_kernel(const float* __restrict__ qkv,
                                                          const int* __restrict__ topH,
                                                          float* __restrict__ kg,
                                                          float* __restrict__ vg)
{
    long i = (long)blockIdx.x * 256 + threadIdx.x;          // 64*32*16*64
    int w = i & 63; long r = i >> 6; int t = (int)(r & 15); r >>= 4;
    int d = (int)(r & 31); int bh = (int)(r >> 5);
    int b = bh >> 3, hh = bh & 7;
    int h = topH[bh * 16 + t];
    long base = (long)b * 768 * HW + (long)(hh * 32 + d) * HW + (long)h * WID + w;
    kg[i] = qkv[base + 256L * HW];
    vg[i] = qkv[base + 512L * HW];
}

// ---------------- score_c + top-16 columns ----------------
__global__ void topw_kernel(const float* __restrict__ qp, const float* __restrict__ kg,
                            int* __restrict__ topW)
{
    __shared__ float sc[64]; __shared__ float qs[32];
    int bh = blockIdx.x, t = threadIdx.x;                  // t = w, 64 threads
    if (t < 32) qs[t] = qp[bh * 32 + t];
    __syncthreads();
    float s = 0.f;
    for (int d = 0; d < 32; d++) {
        float colsum = 0.f;
        #pragma unroll
        for (int i = 0; i < 16; i++)
            colsum += kg[(((long)(bh * 32 + d) * 16) + i) * 64 + t];
        s += qs[d] * colsum;
    }
    sc[t] = s;
    __syncthreads();
    if (t == 0) {
        for (int it = 0; it < 16; it++) {
            float best = -3.4e38f; int bi = 0;
            for (int w = 0; w < 64; w++) if (sc[w] > best) { best = sc[w]; bi = w; }
            topW[bh * 16 + it] = bi; sc[bi] = -3.4e38f;
        }
    }
}

// ---------------- build kf/vf [bh][j][d], j = i*16 + jw ----------------
__global__ __launch_bounds__(256) void build_kv_kernel(const float* __restrict__ kg,
                                                       const float* __restrict__ vg,
                                                       const int* __restrict__ topW,
                                                       float* __restrict__ kf,
                                                       float* __restrict__ vf)
{
    long i = (long)blockIdx.x * 256 + threadIdx.x;          // 64*256*32
    int d = (int)(i & 31); long r = i >> 5; int j = (int)(r & 255); int bh = (int)(r >> 8);
    int ti = j >> 4, jw = j & 15;
    int w = topW[bh * 16 + jw];
    long src = (((long)(bh * 32 + d) * 16) + ti) * 64 + w;
    kf[i] = kg[src]; vf[i] = vg[src];
}

// ---------------- fused sparse attention: softmax(Q Kf^T) Vf ----------------
__global__ __launch_bounds__(128) void attn_kernel(const float* __restrict__ qkv,
                                                   const float* __restrict__ kf,
                                                   const float* __restrict__ vf,
                                                   float* __restrict__ out)
{
    __shared__ float kfs[128 * 32];
    __shared__ float vfs[128 * 32];
    int bh = blockIdx.y;
    int b = bh >> 3, hh = bh & 7;
    int p = blockIdx.x * 128 + threadIdx.x;
    const float* qb = qkv + (long)b * 768 * HW + (long)(hh * 32) * HW + p;
    float q[32], acc[32];
    #pragma unroll
    for (int d = 0; d < 32; d++) { q[d] = qb[(long)d * HW]; acc[d] = 0.f; }
    float l = 0.f;
    for (int ch = 0; ch < 2; ch++) {
        const float4* kc = (const float4*)(kf + ((long)bh * NKEY + ch * 128) * 32);
        const float4* vc = (const float4*)(vf + ((long)bh * NKEY + ch * 128) * 32);
        for (int i = threadIdx.x; i < 1024; i += 128) {
            ((float4*)kfs)[i] = kc[i];
            ((float4*)vfs)[i] = vc[i];
        }
        __syncthreads();
        for (int j = 0; j < 128; j++) {
            const float4* k4 = (const float4*)&kfs[j * 32];
            float s = 0.f;
            #pragma unroll
            for (int d4 = 0; d4 < 8; d4++) {
                float4 kk = k4[d4];
                s += q[d4 * 4 + 0] * kk.x + q[d4 * 4 + 1] * kk.y
                   + q[d4 * 4 + 2] * kk.z + q[d4 * 4 + 3] * kk.w;
            }
            float e = __expf(s);
            l += e;
            const float4* v4 = (const float4*)&vfs[j * 32];
            #pragma unroll
            for (int d4 = 0; d4 < 8; d4++) {
                float4 vv = v4[d4];
                acc[d4 * 4 + 0] = fmaf(e, vv.x, acc[d4 * 4 + 0]);
                acc[d4 * 4 + 1] = fmaf(e, vv.y, acc[d4 * 4 + 1]);
                acc[d4 * 4 + 2] = fmaf(e, vv.z, acc[d4 * 4 + 2]);
                acc[d4 * 4 + 3] = fmaf(e, vv.w, acc[d4 * 4 + 3]);
            }
        }
        __syncthreads();
    }
    float inv = 1.f / l;
    float* ob = out + (long)b * CDIM * HW + (long)(hh * 32) * HW + p;
    #pragma unroll
    for (int d = 0; d < 32; d++) ob[(long)d * HW] = acc[d] * inv;
}

// ---------------- depthwise 3x3 SAME ----------------
__global__ __launch_bounds__(256) void dwconv_kernel(const float* __restrict__ in,
                                                     const float* __restrict__ w,
                                                     const float* __restrict__ bias,
                                                     float* __restrict__ out,
                                                     int C, long inBS, long outBS, int chanOff)
{
    int idx = blockIdx.x;
    int yt = idx & 15; idx >>= 4;
    int c = idx % C; int b = idx / C;
    int x = threadIdx.x & 63;
    int y = yt * 4 + (threadIdx.x >> 6);
    const float* ip = in + (long)b * inBS + (long)c * HW;
    const float* wp = w + c * 9;
    float s = bias[c];
    #pragma unroll
    for (int dy = 0; dy < 3; dy++) {
        int yy = y + dy - 1;
        if (yy < 0 || yy > 63) continue;
        #pragma unroll
        for (int dx = 0; dx < 3; dx++) {
            int xx = x + dx - 1;
            if (xx < 0 || xx > 63) continue;
            s += wp[dy * 3 + dx] * ip[yy * 64 + xx];
        }
    }
    out[(long)b * outBS + (long)(chanOff + c) * HW + y * 64 + x] = s;
}

// ---------------- instance norm (+gelu)(+add) ----------------
__device__ __forceinline__ float gelu_exact(float u)
{
    return 0.5f * u * (1.f + erff(u * 0.7071067811865476f));
}

template <int MODE>  // 0: norm; 1: gelu(norm); 2: add + gelu(norm)
__global__ __launch_bounds__(256) void instnorm_kernel(const float* __restrict__ in,
                                                       const float* __restrict__ addsrc,
                                                       float* __restrict__ out)
{
    __shared__ float sm[16];
    long row = blockIdx.x;
    const float4* p = (const float4*)(in + row * HW);
    int t = threadIdx.x;
    float4 v[4];
    float s = 0.f, s2 = 0.f;
    #pragma unroll
    for (int i = 0; i < 4; i++) {
        v[i] = p[t + i * 256];
        s  += v[i].x + v[i].y + v[i].z + v[i].w;
        s2 += v[i].x * v[i].x + v[i].y * v[i].y + v[i].z * v[i].z + v[i].w * v[i].w;
    }
    #pragma unroll
    for (int o = 16; o > 0; o >>= 1) {
        s  += __shfl_xor_sync(0xffffffffu, s, o);
        s2 += __shfl_xor_sync(0xffffffffu, s2, o);
    }
    if ((t & 31) == 0) { sm[t >> 5] = s; sm[8 + (t >> 5)] = s2; }
    __syncthreads();
    if (t == 0) {
        float a = 0.f, b2 = 0.f;
        for (int i = 0; i < 8; i++) { a += sm[i]; b2 += sm[8 + i]; }
        sm[0] = a; sm[8] = b2;
    }
    __syncthreads();
    float mean = sm[0] * (1.f / HW);
    float var  = sm[8] * (1.f / HW) - mean * mean;
    float inv  = rsqrtf(var + 1e-5f);
    float4* op = (float4*)(out + row * HW);
    const float4* ap = (MODE == 2) ? (const float4*)(addsrc + row * HW) : nullptr;
    #pragma unroll
    for (int i = 0; i < 4; i++) {
        float4 u = v[i];
        u.x = (u.x - mean) * inv; u.y = (u.y - mean) * inv;
        u.z = (u.z - mean) * inv; u.w = (u.w - mean) * inv;
        if (MODE >= 1) {
            u.x = gelu_exact(u.x); u.y = gelu_exact(u.y);
            u.z = gelu_exact(u.z); u.w = gelu_exact(u.w);
        }
        if (MODE == 2) {
            float4 a = ap[t + i * 256];
            u.x += a.x; u.y += a.y; u.z += a.z; u.w += a.w;
        }
        op[t + i * 256] = u;
    }
}

// ---------------- host launcher ----------------
extern "C" void kernel_launch(void* const* d_in, const int* in_sizes, int n_in,
                              void* d_out, int out_size)
{
    (void)in_sizes; (void)n_in; (void)out_size;
    const float* x      = (const float*)d_in[0];
    const float* ln_g   = (const float*)d_in[1];
    const float* ln_b   = (const float*)d_in[2];
    const float* w_qkv  = (const float*)d_in[3];
    const float* w_out  = (const float*)d_in[4];
    const float* b_out  = (const float*)d_in[5];
    const float* w_dw   = (const float*)d_in[6];
    const float* b_dw   = (const float*)d_in[7];
    const float* w_comb = (const float*)d_in[8];
    const float* b_comb = (const float*)d_in[9];
    const float* w_ff1  = (const float*)d_in[10];
    const float* b_ff1  = (const float*)d_in[11];
    const float* w_ffdw = (const float*)d_in[12];
    const float* b_ffdw = (const float*)d_in[13];
    const float* w_ff2  = (const float*)d_in[14];
    const float* b_ff2  = (const float*)d_in[15];
    float* out = (float*)d_out;

    void *p;
    cudaGetSymbolAddress(&p, g_xn);   float* xn   = (float*)p;
    cudaGetSymbolAddress(&p, g_qkv);  float* qkv  = (float*)p;
    cudaGetSymbolAddress(&p, g_attn); float* attn = (float*)p;
    cudaGetSymbolAddress(&p, g_cat);  float* cat  = (float*)p;
    cudaGetSymbolAddress(&p, g_ao);   float* ao   = (float*)p;
    cudaGetSymbolAddress(&p, g_h);    float* h    = (float*)p;
    cudaGetSymbolAddress(&p, g_hg);   float* hg   = (float*)p;
    cudaGetSymbolAddress(&p, g_dwb);  float* dwb  = (float*)p;
    cudaGetSymbolAddress(&p, g_kg);   float* kg   = (float*)p;
    cudaGetSymbolAddress(&p, g_vg);   float* vg   = (float*)p;
    cudaGetSymbolAddress(&p, g_kf);   float* kf   = (float*)p;
    cudaGetSymbolAddress(&p, g_vf);   float* vf   = (float*)p;
    cudaGetSymbolAddress(&p, g_qp);   float* qp   = (float*)p;
    cudaGetSymbolAddress(&p, g_kh);   float* kh   = (float*)p;
    cudaGetSymbolAddress(&p, g_topH); int*   topH = (int*)p;
    cudaGetSymbolAddress(&p, g_topW); int*   topW = (int*)p;

    // allow 66 KB dynamic smem for the GEMM (non-stream call; capture-safe)
    cudaFuncSetAttribute(tgemm_kernel, cudaFuncAttributeMaxDynamicSharedMemorySize,
                         TGEMM_SMEM);

    // 1. channel layernorm
    ln_kernel<<<128, 256>>>(x, ln_g, ln_b, xn);
    // 2. qkv projection (768x256 @ 256x4096, per batch)
    tgemm_kernel<<<dim3(32, 6, BD), 256, TGEMM_SMEM>>>(w_qkv, xn, qkv, 768, HW, 256,
                                           (long)CDIM * HW, (long)768 * HW,
                                           nullptr, nullptr, 0);
    // 3. l2-normalize q,k along W (in place)
    l2norm_kernel<<<32768, 256>>>(qkv);
    // 4. probes + top-k selection
    qprobe_kernel<<<2048, 256>>>(qkv, qp);
    kheight_kernel<<<16384, 256>>>(qkv, kh);
    toph_kernel<<<64, 64>>>(qp, kh, topH);
    gather_rows_kernel<<<8192, 256>>>(qkv, topH, kg, vg);
    topw_kernel<<<64, 64>>>(qp, kg, topW);
    build_kv_kernel<<<2048, 256>>>(kg, vg, topW, kf, vf);
    // 5. fused sparse attention
    attn_kernel<<<dim3(32, NBH), 128>>>(qkv, kf, vf, attn);
    // 6. out-proj into concat buffer rows [0,256)
    tgemm_kernel<<<dim3(32, 2, BD), 256, TGEMM_SMEM>>>(w_out, attn, cat, 256, HW, 256,
                                           (long)CDIM * HW, (long)512 * HW,
                                           b_out, nullptr, 0);
    // 7. dwconv branch into concat buffer rows [256,512)
    dwconv_kernel<<<BD * 256 * 16, 256>>>(x, w_dw, b_dw, cat, 256,
                                          (long)CDIM * HW, (long)512 * HW, 256);
    // 8. combine (K=512) + bias + residual x
    tgemm_kernel<<<dim3(32, 2, BD), 256, TGEMM_SMEM>>>(w_comb, cat, ao, 256, HW, 512,
                                           (long)512 * HW, (long)CDIM * HW,
                                           b_comb, x, (long)CDIM * HW);
    // 9. ff1
    tgemm_kernel<<<dim3(32, 8, BD), 256, TGEMM_SMEM>>>(w_ff1, ao, h, FFI, HW, 256,
                                           (long)CDIM * HW, (long)FFI * HW,
                                           b_ff1, nullptr, 0);
    // 10. h = gelu(instnorm(h))
    instnorm_kernel<1><<<BD * FFI, 256>>>(h, nullptr, hg);
    // 11. dwconv(ffdw)
    dwconv_kernel<<<BD * FFI * 16, 256>>>(hg, w_ffdw, b_ffdw, dwb, FFI,
                                          (long)FFI * HW, (long)FFI * HW, 0);
    // 12. h = hg + gelu(instnorm(dw))
    instnorm_kernel<2><<<BD * FFI, 256>>>(dwb, hg, h);
    // 13. ff2 (reuse xn buffer for output)
    tgemm_kernel<<<dim3(32, 2, BD), 256, TGEMM_SMEM>>>(w_ff2, h, xn, 256, HW, 1024,
                                           (long)FFI * HW, (long)CDIM * HW,
                                           b_ff2, nullptr, 0);
    // 14. final instance norm -> d_out
    instnorm_kernel<0><<<BD * CDIM, 256>>>(xn, nullptr, out);
}

// round 11
// speedup vs baseline: 1.2885x; 1.0001x over previous
#include <cuda_runtime.h>
#include <math.h>
#include <stdint.h>

// ---------------- problem constants ----------------
#define BD     8          // batch
#define HEADS  8
#define DH     32         // dim head
#define CDIM   256        // model dim
#define FFI    1024       // ff inner
#define HW     4096       // 64*64 pixels
#define WID    64
#define NBH    64         // BD*HEADS
#define NKEY   256        // TOP_H * TOP_W

// ---------------- scratch (device globals: no allocs allowed) ----------------
__device__ float g_xn  [(long)BD*CDIM*HW];   // LN(x); reused for ff2 output
__device__ float g_qkv [(long)BD*768*HW];
__device__ float g_attn[(long)BD*CDIM*HW];
__device__ float g_cat [(long)BD*512*HW];
__device__ float g_ao  [(long)BD*CDIM*HW];
__device__ float g_h   [(long)BD*FFI*HW];
__device__ float g_hg  [(long)BD*FFI*HW];
__device__ float g_dwb [(long)BD*FFI*HW];
__device__ float g_kg  [NBH*DH*16*WID];
__device__ float g_vg  [NBH*DH*16*WID];
__device__ float g_kf  [NBH*NKEY*DH];
__device__ float g_vf  [NBH*NKEY*DH];
__device__ float g_qp  [NBH*DH];
__device__ float g_kh  [NBH*DH*WID];
__device__ int   g_topH[NBH*16];
__device__ int   g_topW[NBH*16];

// ---------------- channel layernorm (per pixel over 256 channels) ----------------
__global__ __launch_bounds__(256) void ln_kernel(const float* __restrict__ x,
                                                 const float* __restrict__ g,
                                                 const float* __restrict__ be,
                                                 float* __restrict__ out)
{
    int gp = blockIdx.x * 256 + threadIdx.x;           // 0..32767
    int b = gp >> 12, p = gp & 4095;
    const float* base = x + (long)b * CDIM * HW + p;
    float s = 0.f, s2 = 0.f;
    #pragma unroll 8
    for (int c = 0; c < CDIM; c++) { float v = base[(long)c * HW]; s += v; s2 += v * v; }
    float mean = s * (1.f / CDIM);
    float var  = s2 * (1.f / CDIM) - mean * mean;
    float inv  = rsqrtf(var + 1e-5f);
    float* ob = out + (long)b * CDIM * HW + p;
    #pragma unroll 8
    for (int c = 0; c < CDIM; c++) {
        float v = base[(long)c * HW];
        ob[(long)c * HW] = (v - mean) * inv * g[c] + be[c];
    }
}

// ---------------- TF32x3 tensor-core GEMM, fragment-packed + double-buffered --------
// C[z] = A(MxK) * B[z](KxN) (+bias)(+res).  A row-major shared across batch;
// B/C/res batched by stride.  M,N %128==0, K %16==0.
// 128x128 block tile, 8 warps (2x4), 64x32 warp tile, m16n8k8 tf32 mma.
// Smem holds tiles pre-packed in per-fragment lane layout:
//   A frag (16x8): uint4 per lane, stride 132 words / frag
//   B frag (8x8) : uint2 per lane, stride  66 words / frag
// Double-buffered stages (33792 B each); one __syncthreads per BK=16 iter.

__device__ __forceinline__ uint32_t f2tf(float x)
{
    uint32_t r;
    asm("cvt.rna.tf32.f32 %0, %1;" : "=r"(r) : "f"(x));
    return r;
}

#define MMA_TF32(c, a0, a1, a2, a3, b0, b1) \
    asm volatile("mma.sync.aligned.m16n8k8.row.col.f32.tf32.tf32.f32 " \
        "{%0,%1,%2,%3}, {%4,%5,%6,%7}, {%8,%9}, {%0,%1,%2,%3};" \
        : "+f"((c)[0]), "+f"((c)[1]), "+f"((c)[2]), "+f"((c)[3]) \
        : "r"(a0), "r"(a1), "r"(a2), "r"(a3), "r"(b0), "r"(b1))

#define AFRAG_STRIDE 132     // 128 words + pad
#define BFRAG_STRIDE 66      // 64 words + pad
#define STAGE_WORDS  (2*16*AFRAG_STRIDE + 2*32*BFRAG_STRIDE)   // 8448
#define TGEMM_SMEM   (2 * STAGE_WORDS * 4)                     // 67584 B

__global__ __launch_bounds__(256) void tgemm_kernel(
    const float* __restrict__ A, const float* __restrict__ B, float* __restrict__ C,
    int M, int N, int K, long strideB, long strideC,
    const float* __restrict__ bias, const float* __restrict__ res, long strideRes)
{
    extern __shared__ uint32_t sh[];
    int tid = threadIdx.x;
    int lane = tid & 31, warp = tid >> 5;
    int bx = blockIdx.x * 128, by = blockIdx.y * 128;
    const float* Bp = B + (long)blockIdx.z * strideB;
    float*       Cp = C + (long)blockIdx.z * strideC;

    float acc[4][4][4];
    #pragma unroll
    for (int i = 0; i < 4; i++)
        #pragma unroll
        for (int j = 0; j < 4; j++)
            #pragma unroll
            for (int k = 0; k < 4; k++) acc[i][j][k] = 0.f;

    // -------- staging addresses (per thread, slot-based) --------
    // A: slots s = tid, tid+256 -> frag f=s>>5, lane ls=s&31
    //    element block: m = (f>>1)*16 + (ls>>2), k = (f&1)*8 + (ls&3); gather 4
    // B: idx = tid, tid+256 -> k-row = idx>>5, n-quad = (idx&31)*4 (float4 coalesced)
    int sA0f = tid >> 5, sA0l = tid & 31;
    int sA1f = (tid + 256) >> 5, sA1l = tid & 31;
    long aOff0 = (long)(by + (sA0f >> 1) * 16 + (sA0l >> 2)) * K + (sA0f & 1) * 8 + (sA0l & 3);
    long aOff1 = (long)(by + (sA1f >> 1) * 16 + (sA1l >> 2)) * K + (sA1f & 1) * 8 + (sA1l & 3);
    int bK0 = tid >> 5, bN0 = (tid & 31) * 4;
    int bK1 = (tid + 256) >> 5, bN1 = (tid & 31) * 4;

    float pa[8];
    float4 pb[2];

    // prefetch tile 0
    {
        const float* ap0 = A + aOff0; const float* ap1 = A + aOff1;
        pa[0] = ap0[0]; pa[1] = ap0[8 * K]; pa[2] = ap0[4]; pa[3] = ap0[8 * K + 4];
        pa[4] = ap1[0]; pa[5] = ap1[8 * K]; pa[6] = ap1[4]; pa[7] = ap1[8 * K + 4];
        pb[0] = *(const float4*)(Bp + (long)bK0 * N + bx + bN0);
        pb[1] = *(const float4*)(Bp + (long)bK1 * N + bx + bN1);
    }

    int nIter = K >> 4;

    // stage tile 0 into buffer 0
    {
        uint32_t* AsB = sh;                    uint32_t* AsS = AsB + 16 * AFRAG_STRIDE;
        uint32_t* BsB = AsS + 16 * AFRAG_STRIDE; uint32_t* BsS = BsB + 32 * BFRAG_STRIDE;
        #pragma unroll
        for (int u = 0; u < 2; u++) {
            int f = u ? sA1f : sA0f, ls = u ? sA1l : sA0l;
            uint32_t bg[4], sm[4];
            #pragma unroll
            for (int j = 0; j < 4; j++) {
                float v = pa[u * 4 + j];
                bg[j] = f2tf(v); sm[j] = f2tf(v - __uint_as_float(bg[j]));
            }
            *(uint4*)&AsB[f * AFRAG_STRIDE + ls * 4] = make_uint4(bg[0], bg[1], bg[2], bg[3]);
            *(uint4*)&AsS[f * AFRAG_STRIDE + ls * 4] = make_uint4(sm[0], sm[1], sm[2], sm[3]);
            int kb = u ? bK1 : bK0, nb = u ? bN1 : bN0;
            float bv[4] = { pb[u].x, pb[u].y, pb[u].z, pb[u].w };
            #pragma unroll
            for (int j = 0; j < 4; j++) {
                int n = nb + j;
                int fB = (n >> 3) * 2 + (kb >> 3);
                int bl = ((n & 7) << 2) | (kb & 3);
                int rg = (kb >> 2) & 1;
                uint32_t big = f2tf(bv[j]);
                BsB[fB * BFRAG_STRIDE + bl * 2 + rg] = big;
                BsS[fB * BFRAG_STRIDE + bl * 2 + rg] = f2tf(bv[j] - __uint_as_float(big));
            }
        }
    }
    __syncthreads();

    int wmt = (warp >> 2) * 4;   // mtile base
    int wnt = (warp & 3) * 4;    // ntile base

    for (int it = 0; it < nIter; it++) {
        // prefetch next tile (LDG latency covered by MMA phase)
        if (it + 1 < nIter) {
            int k0 = (it + 1) << 4;
            const float* ap0 = A + aOff0 + k0; const float* ap1 = A + aOff1 + k0;
            pa[0] = ap0[0]; pa[1] = ap0[8 * K]; pa[2] = ap0[4]; pa[3] = ap0[8 * K + 4];
            pa[4] = ap1[0]; pa[5] = ap1[8 * K]; pa[6] = ap1[4]; pa[7] = ap1[8 * K + 4];
            pb[0] = *(const float4*)(Bp + (long)(k0 + bK0) * N + bx + bN0);
            pb[1] = *(const float4*)(Bp + (long)(k0 + bK1) * N + bx + bN1);
        }
        // compute on current buffer
        {
            uint32_t* base = sh + (it & 1) * STAGE_WORDS;
            const uint32_t* AsB = base;
            const uint32_t* AsS = AsB + 16 * AFRAG_STRIDE;
            const uint32_t* BsB = AsS + 16 * AFRAG_STRIDE;
            const uint32_t* BsS = BsB + 32 * BFRAG_STRIDE;
            #pragma unroll
            for (int ks = 0; ks < 2; ks++) {
                uint2 bB[4], bS[4];
                #pragma unroll
                for (int nt = 0; nt < 4; nt++) {
                    int fB = (wnt + nt) * 2 + ks;
                    bB[nt] = *(const uint2*)&BsB[fB * BFRAG_STRIDE + lane * 2];
                    bS[nt] = *(const uint2*)&BsS[fB * BFRAG_STRIDE + lane * 2];
                }
                #pragma unroll
                for (int mt = 0; mt < 4; mt++) {
                    int fA = (wmt + mt) * 2 + ks;
                    uint4 aB = *(const uint4*)&AsB[fA * AFRAG_STRIDE + lane * 4];
                    uint4 aS = *(const uint4*)&AsS[fA * AFRAG_STRIDE + lane * 4];
                    #pragma unroll
                    for (int nt = 0; nt < 4; nt++)
                        MMA_TF32(acc[mt][nt], aB.x, aB.y, aB.z, aB.w, bB[nt].x, bB[nt].y);
                    #pragma unroll
                    for (int nt = 0; nt < 4; nt++)
                        MMA_TF32(acc[mt][nt], aB.x, aB.y, aB.z, aB.w, bS[nt].x, bS[nt].y);
                    #pragma unroll
                    for (int nt = 0; nt < 4; nt++)
                        MMA_TF32(acc[mt][nt], aS.x, aS.y, aS.z, aS.w, bB[nt].x, bB[nt].y);
                }
            }
        }
        // stage next tile into alternate buffer
        if (it + 1 < nIter) {
            uint32_t* base = sh + ((it + 1) & 1) * STAGE_WORDS;
            uint32_t* AsB = base;                    uint32_t* AsS = AsB + 16 * AFRAG_STRIDE;
            uint32_t* BsB = AsS + 16 * AFRAG_STRIDE; uint32_t* BsS = BsB + 32 * BFRAG_STRIDE;
            #pragma unroll
            for (int u = 0; u < 2; u++) {
                int f = u ? sA1f : sA0f, ls = u ? sA1l : sA0l;
                uint32_t bg[4], sm[4];
                #pragma unroll
                for (int j = 0; j < 4; j++) {
                    float v = pa[u * 4 + j];
                    bg[j] = f2tf(v); sm[j] = f2tf(v - __uint_as_float(bg[j]));
                }
                *(uint4*)&AsB[f * AFRAG_STRIDE + ls * 4] = make_uint4(bg[0], bg[1], bg[2], bg[3]);
                *(uint4*)&AsS[f * AFRAG_STRIDE + ls * 4] = make_uint4(sm[0], sm[1], sm[2], sm[3]);
                int kb = u ? bK1 : bK0, nb = u ? bN1 : bN0;
                float bv[4] = { pb[u].x, pb[u].y, pb[u].z, pb[u].w };
                #pragma unroll
                for (int j = 0; j < 4; j++) {
                    int n = nb + j;
                    int fB = (n >> 3) * 2 + (kb >> 3);
                    int bl = ((n & 7) << 2) | (kb & 3);
                    int rg = (kb >> 2) & 1;
                    uint32_t big = f2tf(bv[j]);
                    BsB[fB * BFRAG_STRIDE + bl * 2 + rg] = big;
                    BsS[fB * BFRAG_STRIDE + bl * 2 + rg] = f2tf(bv[j] - __uint_as_float(big));
                }
            }
        }
        __syncthreads();
    }

    // epilogue
    int wm = (warp >> 2) * 64, wn = (warp & 3) * 32;
    int mr = lane >> 2, qc = (lane & 3) * 2;
    #pragma unroll
    for (int mt = 0; mt < 4; mt++) {
        int r0 = by + wm + mt * 16 + mr;
        float bb0 = bias ? bias[r0] : 0.f;
        float bb1 = bias ? bias[r0 + 8] : 0.f;
        #pragma unroll
        for (int nt = 0; nt < 4; nt++) {
            int c = bx + wn + nt * 8 + qc;
            long o0 = (long)r0 * N + c;
            long o1 = (long)(r0 + 8) * N + c;
            float2 v0 = make_float2(acc[mt][nt][0] + bb0, acc[mt][nt][1] + bb0);
            float2 v1 = make_float2(acc[mt][nt][2] + bb1, acc[mt][nt][3] + bb1);
            if (res) {
                const float* rp = res + (long)blockIdx.z * strideRes;
                v0.x += rp[o0]; v0.y += rp[o0 + 1];
                v1.x += rp[o1]; v1.y += rp[o1 + 1];
            }
            *(float2*)&Cp[o0] = v0;
            *(float2*)&Cp[o1] = v1;
        }
    }
}

// ---------------- l2-normalize q,k rows (along W=64) in place ----------------
__global__ __launch_bounds__(256) void l2norm_kernel(float* __restrict__ qkv)
{
    int gt = blockIdx.x * 256 + threadIdx.x;
    int warp = gt >> 5, lane = gt & 31;
    if (warp >= BD * 512 * WID) return;
    int b = warp / (512 * WID);
    int rem = warp % (512 * WID);
    float* p = qkv + (long)b * 768 * HW + (long)rem * WID;
    float v0 = p[lane], v1 = p[lane + 32];
    float s = v0 * v0 + v1 * v1;
    #pragma unroll
    for (int o = 16; o > 0; o >>= 1) s += __shfl_xor_sync(0xffffffffu, s, o);
    float scale = 1.f / fmaxf(sqrtf(s), 1e-12f);
    p[lane] = v0 * scale; p[lane + 32] = v1 * scale;
}

// ---------------- q_probe[bh][d] = sum over all pixels of normalized q ----------------
__global__ __launch_bounds__(256) void qprobe_kernel(const float* __restrict__ qkv,
                                                     float* __restrict__ qp)
{
    __shared__ float sm[8];
    int c = blockIdx.x;                     // 0..2047 = bh*32+d
    int bh = c >> 5, d = c & 31, b = bh >> 3, hh = bh & 7;
    const float* p = qkv + (long)b * 768 * HW + (long)(hh * 32 + d) * HW;
    float s = 0.f;
    for (int i = threadIdx.x; i < HW; i += 256) s += p[i];
    #pragma unroll
    for (int o = 16; o > 0; o >>= 1) s += __shfl_xor_sync(0xffffffffu, s, o);
    if ((threadIdx.x & 31) == 0) sm[threadIdx.x >> 5] = s;
    __syncthreads();
    if (threadIdx.x == 0) { float t = 0; for (int i = 0; i < 8; i++) t += sm[i]; qp[c] = t; }
}

// ---------------- k_height[bh][d][h] = sum over w of normalized k ----------------
__global__ __launch_bounds__(256) void kheight_kernel(const float* __restrict__ qkv,
                                                      float* __restrict__ kh)
{
    int gt = blockIdx.x * 256 + threadIdx.x;
    int warp = gt >> 5, lane = gt & 31;
    if (warp >= NBH * DH * WID) return;
    int h = warp & 63; int rest = warp >> 6; int d = rest & 31; int bh = rest >> 5;
    int b = bh >> 3, hh = bh & 7;
    const float* p = qkv + (long)b * 768 * HW + (long)(256 + hh * 32 + d) * HW + h * WID;
    float s = p[lane] + p[lane + 32];
    #pragma unroll
    for (int o = 16; o > 0; o >>= 1) s += __shfl_xor_sync(0xffffffffu, s, o);
    if (lane == 0) kh[warp] = s;
}

// ---------------- score_r + top-16 rows (set only; order irrelevant downstream) ---------
__global__ void toph_kernel(const float* __restrict__ qp, const float* __restrict__ kh,
                            int* __restrict__ topH)
{
    __shared__ float sc[64]; __shared__ float qs[32];
    int bh = blockIdx.x, t = threadIdx.x;                  // 64 threads
    if (t < 32) qs[t] = qp[bh * 32 + t];
    __syncthreads();
    float s = 0.f;
    #pragma unroll
    for (int d = 0; d < 32; d++) s += qs[d] * kh[((bh * 32 + d) << 6) + t];
    sc[t] = s;
    __syncthreads();
    if (t == 0) {
        for (int it = 0; it < 16; it++) {
            float best = -3.4e38f; int bi = 0;
            for (int h = 0; h < 64; h++) if (sc[h] > best) { best = sc[h]; bi = h; }
            topH[bh * 16 + it] = bi; sc[bi] = -3.4e38f;
        }
    }
}

// ---------------- gather selected rows of k,v -> kg/vg [bh][d][16][64] -----------------
__global__ __launch_bounds__(256) void gather_rows_kernel(const float* __restrict__ qkv,
                                                          const int* __restrict__ topH,
                                                          float* __restrict__ kg,
                                                          float* __restrict__ vg)
{
    long i = (long)blockIdx.x * 256 + threadIdx.x;          // 64*32*16*64
    int w = i & 63; long r = i >> 6; int t = (int)(r & 15); r >>= 4;
    int d = (int)(r & 31); int bh = (int)(r >> 5);
    int b = bh >> 3, hh = bh & 7;
    int h = topH[bh * 16 + t];
    long base = (long)b * 768 * HW + (long)(hh * 32 + d) * HW + (long)h * WID + w;
    kg[i] = qkv[base + 256L * HW];
    vg[i] = qkv[base + 512L * HW];
}

// ---------------- score_c + top-16 columns ----------------
__global__ void topw_kernel(const float* __restrict__ qp, const float* __restrict__ kg,
                            int* __restrict__ topW)
{
    __shared__ float sc[64]; __shared__ float qs[32];
    int bh = blockIdx.x, t = threadIdx.x;                  // t = w, 64 threads
    if (t < 32) qs[t] = qp[bh * 32 + t];
    __syncthreads();
    float s = 0.f;
    for (int d = 0; d < 32; d++) {
        float colsum = 0.f;
        #pragma unroll
        for (int i = 0; i < 16; i++)
            colsum += kg[(((long)(bh * 32 + d) * 16) + i) * 64 + t];
        s += qs[d] * colsum;
    }
    sc[t] = s;
    __syncthreads();
    if (t == 0) {
        for (int it = 0; it < 16; it++) {
            float best = -3.4e38f; int bi = 0;
            for (int w = 0; w < 64; w++) if (sc[w] > best) { best = sc[w]; bi = w; }
            topW[bh * 16 + it] = bi; sc[bi] = -3.4e38f;
        }
    }
}

// ---------------- build kf/vf [bh][j][d], j = i*16 + jw ----------------
__global__ __launch_bounds__(256) void build_kv_kernel(const float* __restrict__ kg,
                                                       const float* __restrict__ vg,
                                                       const int* __restrict__ topW,
                                                       float* __restrict__ kf,
                                                       float* __restrict__ vf)
{
    long i = (long)blockIdx.x * 256 + threadIdx.x;          // 64*256*32
    int d = (int)(i & 31); long r = i >> 5; int j = (int)(r & 255); int bh = (int)(r >> 8);
    int ti = j >> 4, jw = j & 15;
    int w = topW[bh * 16 + jw];
    long src = (((long)(bh * 32 + d) * 16) + ti) * 64 + w;
    kf[i] = kg[src]; vf[i] = vg[src];
}

// ---------------- fused sparse attention: softmax(Q Kf^T) Vf ----------------
__global__ __launch_bounds__(128) void attn_kernel(const float* __restrict__ qkv,
                                                   const float* __restrict__ kf,
                                                   const float* __restrict__ vf,
                                                   float* __restrict__ out)
{
    __shared__ float kfs[128 * 32];
    __shared__ float vfs[128 * 32];
    int bh = blockIdx.y;
    int b = bh >> 3, hh = bh & 7;
    int p = blockIdx.x * 128 + threadIdx.x;
    const float* qb = qkv + (long)b * 768 * HW + (long)(hh * 32) * HW + p;
    float q[32], acc[32];
    #pragma unroll
    for (int d = 0; d < 32; d++) { q[d] = qb[(long)d * HW]; acc[d] = 0.f; }
    float l = 0.f;
    for (int ch = 0; ch < 2; ch++) {
        const float4* kc = (const float4*)(kf + ((long)bh * NKEY + ch * 128) * 32);
        const float4* vc = (const float4*)(vf + ((long)bh * NKEY + ch * 128) * 32);
        for (int i = threadIdx.x; i < 1024; i += 128) {
            ((float4*)kfs)[i] = kc[i];
            ((float4*)vfs)[i] = vc[i];
        }
        __syncthreads();
        for (int j = 0; j < 128; j++) {
            const float4* k4 = (const float4*)&kfs[j * 32];
            float s = 0.f;
            #pragma unroll
            for (int d4 = 0; d4 < 8; d4++) {
                float4 kk = k4[d4];
                s += q[d4 * 4 + 0] * kk.x + q[d4 * 4 + 1] * kk.y
                   + q[d4 * 4 + 2] * kk.z + q[d4 * 4 + 3] * kk.w;
            }
            float e = __expf(s);
            l += e;
            const float4* v4 = (const float4*)&vfs[j * 32];
            #pragma unroll
            for (int d4 = 0; d4 < 8; d4++) {
                float4 vv = v4[d4];
                acc[d4 * 4 + 0] = fmaf(e, vv.x, acc[d4 * 4 + 0]);
                acc[d4 * 4 + 1] = fmaf(e, vv.y, acc[d4 * 4 + 1]);
                acc[d4 * 4 + 2] = fmaf(e, vv.z, acc[d4 * 4 + 2]);
                acc[d4 * 4 + 3] = fmaf(e, vv.w, acc[d4 * 4 + 3]);
            }
        }
        __syncthreads();
    }
    float inv = 1.f / l;
    float* ob = out + (long)b * CDIM * HW + (long)(hh * 32) * HW + p;
    #pragma unroll
    for (int d = 0; d < 32; d++) ob[(long)d * HW] = acc[d] * inv;
}

// ---------------- depthwise 3x3 SAME ----------------
__global__ __launch_bounds__(256) void dwconv_kernel(const float* __restrict__ in,
                                                     const float* __restrict__ w,
                                                     const float* __restrict__ bias,
                                                     float* __restrict__ out,
                                                     int C, long inBS, long outBS, int chanOff)
{
    int idx = blockIdx.x;
    int yt = idx & 15; idx >>= 4;
    int c = idx % C; int b = idx / C;
    int x = threadIdx.x & 63;
    int y = yt * 4 + (threadIdx.x >> 6);
    const float* ip = in + (long)b * inBS + (long)c * HW;
    const float* wp = w + c * 9;
    float s = bias[c];
    #pragma unroll
    for (int dy = 0; dy < 3; dy++) {
        int yy = y + dy - 1;
        if (yy < 0 || yy > 63) continue;
        #pragma unroll
        for (int dx = 0; dx < 3; dx++) {
            int xx = x + dx - 1;
            if (xx < 0 || xx > 63) continue;
            s += wp[dy * 3 + dx] * ip[yy * 64 + xx];
        }
    }
    out[(long)b * outBS + (long)(chanOff + c) * HW + y * 64 + x] = s;
}

// ---------------- instance norm (+gelu)(+add) ----------------
__device__ __forceinline__ float gelu_exact(float u)
{
    return 0.5f * u * (1.f + erff(u * 0.7071067811865476f));
}

template <int MODE>  // 0: norm; 1: gelu(norm); 2: add + gelu(norm)
__global__ __launch_bounds__(256) void instnorm_kernel(const float* __restrict__ in,
                                                       const float* __restrict__ addsrc,
                                                       float* __restrict__ out)
{
    __shared__ float sm[16];
    long row = blockIdx.x;
    const float4* p = (const float4*)(in + row * HW);
    int t = threadIdx.x;
    float4 v[4];
    float s = 0.f, s2 = 0.f;
    #pragma unroll
    for (int i = 0; i < 4; i++) {
        v[i] = p[t + i * 256];
        s  += v[i].x + v[i].y + v[i].z + v[i].w;
        s2 += v[i].x * v[i].x + v[i].y * v[i].y + v[i].z * v[i].z + v[i].w * v[i].w;
    }
    #pragma unroll
    for (int o = 16; o > 0; o >>= 1) {
        s  += __shfl_xor_sync(0xffffffffu, s, o);
        s2 += __shfl_xor_sync(0xffffffffu, s2, o);
    }
    if ((t & 31) == 0) { sm[t >> 5] = s; sm[8 + (t >> 5)] = s2; }
    __syncthreads();
    if (t == 0) {
        float a = 0.f, b2 = 0.f;
        for (int i = 0; i < 8; i++) { a += sm[i]; b2 += sm[8 + i]; }
        sm[0] = a; sm[8] = b2;
    }
    __syncthreads();
    float mean = sm[0] * (1.f / HW);
    float var  = sm[8] * (1.f / HW) - mean * mean;
    float inv  = rsqrtf(var + 1e-5f);
    float4* op = (float4*)(out + row * HW);
    const float4* ap = (MODE == 2) ? (const float4*)(addsrc + row * HW) : nullptr;
    #pragma unroll
    for (int i = 0; i < 4; i++) {
        float4 u = v[i];
        u.x = (u.x - mean) * inv; u.y = (u.y - mean) * inv;
        u.z = (u.z - mean) * inv; u.w = (u.w - mean) * inv;
        if (MODE >= 1) {
            u.x = gelu_exact(u.x); u.y = gelu_exact(u.y);
            u.z = gelu_exact(u.z); u.w = gelu_exact(u.w);
        }
        if (MODE == 2) {
            float4 a = ap[t + i * 256];
            u.x += a.x; u.y += a.y; u.z += a.z; u.w += a.w;
        }
        op[t + i * 256] = u;
    }
}

// ---------------- host launcher ----------------
extern "C" void kernel_launch(void* const* d_in, const int* in_sizes, int n_in,
                              void* d_out, int out_size)
{
    (void)in_sizes; (void)n_in; (void)out_size;
    const float* x      = (const float*)d_in[0];
    const float* ln_g   = (const float*)d_in[1];
    const float* ln_b   = (const float*)d_in[2];
    const float* w_qkv  = (const float*)d_in[3];
    const float* w_out  = (const float*)d_in[4];
    const float* b_out  = (const float*)d_in[5];
    const float* w_dw   = (const float*)d_in[6];
    const float* b_dw   = (const float*)d_in[7];
    const float* w_comb = (const float*)d_in[8];
    const float* b_comb = (const float*)d_in[9];
    const float* w_ff1  = (const float*)d_in[10];
    const float* b_ff1  = (const float*)d_in[11];
    const float* w_ffdw = (const float*)d_in[12];
    const float* b_ffdw = (const float*)d_in[13];
    const float* w_ff2  = (const float*)d_in[14];
    const float* b_ff2  = (const float*)d_in[15];
    float* out = (float*)d_out;

    void *p;
    cudaGetSymbolAddress(&p, g_xn);   float* xn   = (float*)p;
    cudaGetSymbolAddress(&p, g_qkv);  float* qkv  = (float*)p;
    cudaGetSymbolAddress(&p, g_attn); float* attn = (float*)p;
    cudaGetSymbolAddress(&p, g_cat);  float* cat  = (float*)p;
    cudaGetSymbolAddress(&p, g_ao);   float* ao   = (float*)p;
    cudaGetSymbolAddress(&p, g_h);    float* h    = (float*)p;
    cudaGetSymbolAddress(&p, g_hg);   float* hg   = (float*)p;
    cudaGetSymbolAddress(&p, g_dwb);  float* dwb  = (float*)p;
    cudaGetSymbolAddress(&p, g_kg);   float* kg   = (float*)p;
    cudaGetSymbolAddress(&p, g_vg);   float* vg   = (float*)p;
    cudaGetSymbolAddress(&p, g_kf);   float* kf   = (float*)p;
    cudaGetSymbolAddress(&p, g_vf);   float* vf   = (float*)p;
    cudaGetSymbolAddress(&p, g_qp);   float* qp   = (float*)p;
    cudaGetSymbolAddress(&p, g_kh);   float* kh   = (float*)p;
    cudaGetSymbolAddress(&p, g_topH); int*   topH = (int*)p;
    cudaGetSymbolAddress(&p, g_topW); int*   topW = (int*)p;

    // allow 66 KB dynamic smem for the GEMM (non-stream call; capture-safe)
    cudaFuncSetAttribute(tgemm_kernel, cudaFuncAttributeMaxDynamicSharedMemorySize,
                         TGEMM_SMEM);

    // 1. channel layernorm
    ln_kernel<<<128, 256>>>(x, ln_g, ln_b, xn);
    // 2. qkv projection (768x256 @ 256x4096, per batch)
    tgemm_kernel<<<dim3(32, 6, BD), 256, TGEMM_SMEM>>>(w_qkv, xn, qkv, 768, HW, 256,
                                           (long)CDIM * HW, (long)768 * HW,
                                           nullptr, nullptr, 0);
    // 3. l2-normalize q,k along W (in place)
    l2norm_kernel<<<32768, 256>>>(qkv);
    // 4. probes + top-k selection
    qprobe_kernel<<<2048, 256>>>(qkv, qp);
    kheight_kernel<<<16384, 256>>>(qkv, kh);
    toph_kernel<<<64, 64>>>(qp, kh, topH);
    gather_rows_kernel<<<8192, 256>>>(qkv, topH, kg, vg);
    topw_kernel<<<64, 64>>>(qp, kg, topW);
    build_kv_kernel<<<2048, 256>>>(kg, vg, topW, kf, vf);
    // 5. fused sparse attention
    attn_kernel<<<dim3(32, NBH), 128>>>(qkv, kf, vf, attn);
    // 6. out-proj into concat buffer rows [0,256)
    tgemm_kernel<<<dim3(32, 2, BD), 256, TGEMM_SMEM>>>(w_out, attn, cat, 256, HW, 256,
                                           (long)CDIM * HW, (long)512 * HW,
                                           b_out, nullptr, 0);
    // 7. dwconv branch into concat buffer rows [256,512)
    dwconv_kernel<<<BD * 256 * 16, 256>>>(x, w_dw, b_dw, cat, 256,
                                          (long)CDIM * HW, (long)512 * HW, 256);
    // 8. combine (K=512) + bias + residual x
    tgemm_kernel<<<dim3(32, 2, BD), 256, TGEMM_SMEM>>>(w_comb, cat, ao, 256, HW, 512,
                                           (long)512 * HW, (long)CDIM * HW,
                                           b_comb, x, (long)CDIM * HW);
    // 9. ff1
    tgemm_kernel<<<dim3(32, 8, BD), 256, TGEMM_SMEM>>>(w_ff1, ao, h, FFI, HW, 256,
                                           (long)CDIM * HW, (long)FFI * HW,
                                           b_ff1, nullptr, 0);
    // 10. h = gelu(instnorm(h))
    instnorm_kernel<1><<<BD * FFI, 256>>>(h, nullptr, hg);
    // 11. dwconv(ffdw)
    dwconv_kernel<<<BD * FFI * 16, 256>>>(hg, w_ffdw, b_ffdw, dwb, FFI,
                                          (long)FFI * HW, (long)FFI * HW, 0);
    // 12. h = hg + gelu(instnorm(dw))
    instnorm_kernel<2><<<BD * FFI, 256>>>(dwb, hg, h);
    // 13. ff2 (reuse xn buffer for output)
    tgemm_kernel<<<dim3(32, 2, BD), 256, TGEMM_SMEM>>>(w_ff2, h, xn, 256, HW, 1024,
                                           (long)FFI * HW, (long)CDIM * HW,
                                           b_ff2, nullptr, 0);
    // 14. final instance norm -> d_out
    instnorm_kernel<0><<<BD * CDIM, 256>>>(xn, nullptr, out);
}

// round 12
// speedup vs baseline: 1.5865x; 1.2313x over previous
#include <cuda_runtime.h>
#include <cuda_bf16.h>
#include <math.h>
#include <stdint.h>

// ---------------- problem constants ----------------
#define BD     8          // batch
#define HEADS  8
#define DH     32         // dim head
#define CDIM   256        // model dim
#define FFI    1024       // ff inner
#define HW     4096       // 64*64 pixels
#define WID    64
#define NBH    64         // BD*HEADS
#define NKEY   256        // TOP_H * TOP_W

// ---------------- scratch (device globals: no allocs allowed) ----------------
__device__ float g_xn  [(long)BD*CDIM*HW];   // LN(x); reused for ff2 output
__device__ float g_qkv [(long)BD*768*HW];
__device__ float g_attn[(long)BD*CDIM*HW];
__device__ float g_cat [(long)BD*512*HW];
__device__ float g_ao  [(long)BD*CDIM*HW];
__device__ float g_h   [(long)BD*FFI*HW];
__device__ float g_hg  [(long)BD*FFI*HW];
__device__ float g_kg  [NBH*DH*16*WID];
__device__ float g_vg  [NBH*DH*16*WID];
__device__ uint32_t g_kf [NBH*NKEY*16];      // bf16x2 packed
__device__ uint32_t g_vf [NBH*NKEY*16];
__device__ float g_qp  [NBH*DH];
__device__ float g_kh  [NBH*DH*WID];
__device__ int   g_topH[NBH*16];
__device__ int   g_topW[NBH*16];

// ---------------- channel layernorm (per pixel over 256 channels) ----------------
__global__ __launch_bounds__(256) void ln_kernel(const float* __restrict__ x,
                                                 const float* __restrict__ g,
                                                 const float* __restrict__ be,
                                                 float* __restrict__ out)
{
    int gp = blockIdx.x * 256 + threadIdx.x;           // 0..32767
    int b = gp >> 12, p = gp & 4095;
    const float* base = x + (long)b * CDIM * HW + p;
    float s = 0.f, s2 = 0.f;
    #pragma unroll 8
    for (int c = 0; c < CDIM; c++) { float v = base[(long)c * HW]; s += v; s2 += v * v; }
    float mean = s * (1.f / CDIM);
    float var  = s2 * (1.f / CDIM) - mean * mean;
    float inv  = rsqrtf(var + 1e-5f);
    float* ob = out + (long)b * CDIM * HW + p;
    #pragma unroll 8
    for (int c = 0; c < CDIM; c++) {
        float v = base[(long)c * HW];
        ob[(long)c * HW] = (v - mean) * inv * g[c] + be[c];
    }
}

// ---------------- TF32 tensor-core GEMM, fragment-packed + double-buffered --------
// C[z] = A(MxK) * B[z](KxN) (+bias)(+res).  A row-major shared across batch;
// B/C/res batched by stride.  M,N %128==0, K %16==0.
// 128x128 block tile, 8 warps (2x4), 64x32 warp tile, m16n8k8 tf32 mma.
// S3=1: 3xTF32 (bb+bs+sb) near-fp32 accuracy.  S3=0: single-pass TF32.

__device__ __forceinline__ uint32_t f2tf(float x)
{
    uint32_t r;
    asm("cvt.rna.tf32.f32 %0, %1;" : "=r"(r) : "f"(x));
    return r;
}

#define MMA_TF32(c, a0, a1, a2, a3, b0, b1) \
    asm volatile("mma.sync.aligned.m16n8k8.row.col.f32.tf32.tf32.f32 " \
        "{%0,%1,%2,%3}, {%4,%5,%6,%7}, {%8,%9}, {%0,%1,%2,%3};" \
        : "+f"((c)[0]), "+f"((c)[1]), "+f"((c)[2]), "+f"((c)[3]) \
        : "r"(a0), "r"(a1), "r"(a2), "r"(a3), "r"(b0), "r"(b1))

#define AFRAG_STRIDE 132     // 128 words + pad
#define BFRAG_STRIDE 66      // 64 words + pad
#define AWORDS (16 * AFRAG_STRIDE)
#define BWORDS (32 * BFRAG_STRIDE)
#define TGEMM_SMEM(S3) (2 * ((S3) ? 2 : 1) * (AWORDS + BWORDS) * 4)

template <int S3>
__global__ __launch_bounds__(256) void tgemm_kernel(
    const float* __restrict__ A, const float* __restrict__ B, float* __restrict__ C,
    int M, int N, int K, long strideB, long strideC,
    const float* __restrict__ bias, const float* __restrict__ res, long strideRes)
{
    constexpr int STAGE = (S3 ? 2 : 1) * (AWORDS + BWORDS);
    extern __shared__ uint32_t sh[];
    int tid = threadIdx.x;
    int lane = tid & 31, warp = tid >> 5;
    int bx = blockIdx.x * 128, by = blockIdx.y * 128;
    const float* Bp = B + (long)blockIdx.z * strideB;
    float*       Cp = C + (long)blockIdx.z * strideC;

    float acc[4][4][4];
    #pragma unroll
    for (int i = 0; i < 4; i++)
        #pragma unroll
        for (int j = 0; j < 4; j++)
            #pragma unroll
            for (int k = 0; k < 4; k++) acc[i][j][k] = 0.f;

    int sA0f = tid >> 5, sA0l = tid & 31;
    int sA1f = (tid + 256) >> 5, sA1l = tid & 31;
    long aOff0 = (long)(by + (sA0f >> 1) * 16 + (sA0l >> 2)) * K + (sA0f & 1) * 8 + (sA0l & 3);
    long aOff1 = (long)(by + (sA1f >> 1) * 16 + (sA1l >> 2)) * K + (sA1f & 1) * 8 + (sA1l & 3);
    int bK0 = tid >> 5, bN0 = (tid & 31) * 4;
    int bK1 = (tid + 256) >> 5, bN1 = (tid & 31) * 4;

    float pa[8];
    float4 pb[2];

    {
        const float* ap0 = A + aOff0; const float* ap1 = A + aOff1;
        pa[0] = ap0[0]; pa[1] = ap0[8 * K]; pa[2] = ap0[4]; pa[3] = ap0[8 * K + 4];
        pa[4] = ap1[0]; pa[5] = ap1[8 * K]; pa[6] = ap1[4]; pa[7] = ap1[8 * K + 4];
        pb[0] = *(const float4*)(Bp + (long)bK0 * N + bx + bN0);
        pb[1] = *(const float4*)(Bp + (long)bK1 * N + bx + bN1);
    }

    int nIter = K >> 4;

    // stage helper (macro-free lambda)
    auto stage = [&](uint32_t* base) {
        uint32_t* AsB = base;
        uint32_t* AsS = base + AWORDS;
        uint32_t* BsB = base + (S3 ? 2 : 1) * AWORDS;
        uint32_t* BsS = BsB + BWORDS;
        #pragma unroll
        for (int u = 0; u < 2; u++) {
            int f = u ? sA1f : sA0f, ls = u ? sA1l : sA0l;
            uint32_t bg[4], sm[4];
            #pragma unroll
            for (int j = 0; j < 4; j++) {
                float v = pa[u * 4 + j];
                bg[j] = f2tf(v);
                if (S3) sm[j] = f2tf(v - __uint_as_float(bg[j]));
            }
            *(uint4*)&AsB[f * AFRAG_STRIDE + ls * 4] = make_uint4(bg[0], bg[1], bg[2], bg[3]);
            if (S3)
                *(uint4*)&AsS[f * AFRAG_STRIDE + ls * 4] = make_uint4(sm[0], sm[1], sm[2], sm[3]);
            int kb = u ? bK1 : bK0, nb = u ? bN1 : bN0;
            float bv[4] = { pb[u].x, pb[u].y, pb[u].z, pb[u].w };
            #pragma unroll
            for (int j = 0; j < 4; j++) {
                int n = nb + j;
                int fB = (n >> 3) * 2 + (kb >> 3);
                int bl = ((n & 7) << 2) | (kb & 3);
                int rg = (kb >> 2) & 1;
                uint32_t big = f2tf(bv[j]);
                BsB[fB * BFRAG_STRIDE + bl * 2 + rg] = big;
                if (S3)
                    BsS[fB * BFRAG_STRIDE + bl * 2 + rg] = f2tf(bv[j] - __uint_as_float(big));
            }
        }
    };

    stage(sh);
    __syncthreads();

    int wmt = (warp >> 2) * 4;
    int wnt = (warp & 3) * 4;

    for (int it = 0; it < nIter; it++) {
        if (it + 1 < nIter) {
            int k0 = (it + 1) << 4;
            const float* ap0 = A + aOff0 + k0; const float* ap1 = A + aOff1 + k0;
            pa[0] = ap0[0]; pa[1] = ap0[8 * K]; pa[2] = ap0[4]; pa[3] = ap0[8 * K + 4];
            pa[4] = ap1[0]; pa[5] = ap1[8 * K]; pa[6] = ap1[4]; pa[7] = ap1[8 * K + 4];
            pb[0] = *(const float4*)(Bp + (long)(k0 + bK0) * N + bx + bN0);
            pb[1] = *(const float4*)(Bp + (long)(k0 + bK1) * N + bx + bN1);
        }
        {
            uint32_t* base = sh + (it & 1) * STAGE;
            const uint32_t* AsB = base;
            const uint32_t* AsS = base + AWORDS;
            const uint32_t* BsB = base + (S3 ? 2 : 1) * AWORDS;
            const uint32_t* BsS = BsB + BWORDS;
            #pragma unroll
            for (int ks = 0; ks < 2; ks++) {
                uint2 bB[4], bS[4];
                #pragma unroll
                for (int nt = 0; nt < 4; nt++) {
                    int fB = (wnt + nt) * 2 + ks;
                    bB[nt] = *(const uint2*)&BsB[fB * BFRAG_STRIDE + lane * 2];
                    if (S3) bS[nt] = *(const uint2*)&BsS[fB * BFRAG_STRIDE + lane * 2];
                }
                #pragma unroll
                for (int mt = 0; mt < 4; mt++) {
                    int fA = (wmt + mt) * 2 + ks;
                    uint4 aB = *(const uint4*)&AsB[fA * AFRAG_STRIDE + lane * 4];
                    #pragma unroll
                    for (int nt = 0; nt < 4; nt++)
                        MMA_TF32(acc[mt][nt], aB.x, aB.y, aB.z, aB.w, bB[nt].x, bB[nt].y);
                    if (S3) {
                        uint4 aS = *(const uint4*)&AsS[fA * AFRAG_STRIDE + lane * 4];
                        #pragma unroll
                        for (int nt = 0; nt < 4; nt++)
                            MMA_TF32(acc[mt][nt], aB.x, aB.y, aB.z, aB.w, bS[nt].x, bS[nt].y);
                        #pragma unroll
                        for (int nt = 0; nt < 4; nt++)
                            MMA_TF32(acc[mt][nt], aS.x, aS.y, aS.z, aS.w, bB[nt].x, bB[nt].y);
                    }
                }
            }
        }
        if (it + 1 < nIter) stage(sh + ((it + 1) & 1) * STAGE);
        __syncthreads();
    }

    int wm = (warp >> 2) * 64, wn = (warp & 3) * 32;
    int mr = lane >> 2, qc = (lane & 3) * 2;
    #pragma unroll
    for (int mt = 0; mt < 4; mt++) {
        int r0 = by + wm + mt * 16 + mr;
        float bb0 = bias ? bias[r0] : 0.f;
        float bb1 = bias ? bias[r0 + 8] : 0.f;
        #pragma unroll
        for (int nt = 0; nt < 4; nt++) {
            int c = bx + wn + nt * 8 + qc;
            long o0 = (long)r0 * N + c;
            long o1 = (long)(r0 + 8) * N + c;
            float2 v0 = make_float2(acc[mt][nt][0] + bb0, acc[mt][nt][1] + bb0);
            float2 v1 = make_float2(acc[mt][nt][2] + bb1, acc[mt][nt][3] + bb1);
            if (res) {
                const float* rp = res + (long)blockIdx.z * strideRes;
                v0.x += rp[o0]; v0.y += rp[o0 + 1];
                v1.x += rp[o1]; v1.y += rp[o1 + 1];
            }
            *(float2*)&Cp[o0] = v0;
            *(float2*)&Cp[o1] = v1;
        }
    }
}

// ---------------- l2-normalize q,k rows (along W=64) in place ----------------
__global__ __launch_bounds__(256) void l2norm_kernel(float* __restrict__ qkv)
{
    int gt = blockIdx.x * 256 + threadIdx.x;
    int warp = gt >> 5, lane = gt & 31;
    if (warp >= BD * 512 * WID) return;
    int b = warp / (512 * WID);
    int rem = warp % (512 * WID);
    float* p = qkv + (long)b * 768 * HW + (long)rem * WID;
    float v0 = p[lane], v1 = p[lane + 32];
    float s = v0 * v0 + v1 * v1;
    #pragma unroll
    for (int o = 16; o > 0; o >>= 1) s += __shfl_xor_sync(0xffffffffu, s, o);
    float scale = 1.f / fmaxf(sqrtf(s), 1e-12f);
    p[lane] = v0 * scale; p[lane + 32] = v1 * scale;
}

// ---------------- q_probe[bh][d] = sum over all pixels of normalized q ----------------
__global__ __launch_bounds__(256) void qprobe_kernel(const float* __restrict__ qkv,
                                                     float* __restrict__ qp)
{
    __shared__ float sm[8];
    int c = blockIdx.x;                     // 0..2047 = bh*32+d
    int bh = c >> 5, d = c & 31, b = bh >> 3, hh = bh & 7;
    const float4* p = (const float4*)(qkv + (long)b * 768 * HW + (long)(hh * 32 + d) * HW);
    float s = 0.f;
    #pragma unroll
    for (int i = 0; i < 4; i++) {
        float4 v = p[threadIdx.x + i * 256];
        s += v.x + v.y + v.z + v.w;
    }
    #pragma unroll
    for (int o = 16; o > 0; o >>= 1) s += __shfl_xor_sync(0xffffffffu, s, o);
    if ((threadIdx.x & 31) == 0) sm[threadIdx.x >> 5] = s;
    __syncthreads();
    if (threadIdx.x == 0) { float t = 0; for (int i = 0; i < 8; i++) t += sm[i]; qp[c] = t; }
}

// ---------------- k_height[bh][d][h] = sum over w of normalized k ----------------
__global__ __launch_bounds__(256) void kheight_kernel(const float* __restrict__ qkv,
                                                      float* __restrict__ kh)
{
    int gt = blockIdx.x * 256 + threadIdx.x;
    int warp = gt >> 5, lane = gt & 31;
    if (warp >= NBH * DH * WID) return;
    int h = warp & 63; int rest = warp >> 6; int d = rest & 31; int bh = rest >> 5;
    int b = bh >> 3, hh = bh & 7;
    const float* p = qkv + (long)b * 768 * HW + (long)(256 + hh * 32 + d) * HW + h * WID;
    float s = p[lane] + p[lane + 32];
    #pragma unroll
    for (int o = 16; o > 0; o >>= 1) s += __shfl_xor_sync(0xffffffffu, s, o);
    if (lane == 0) kh[warp] = s;
}

// ---------------- score_r + top-16 rows (set only; order irrelevant downstream) ---------
__global__ void toph_kernel(const float* __restrict__ qp, const float* __restrict__ kh,
                            int* __restrict__ topH)
{
    __shared__ float sc[64]; __shared__ float qs[32];
    int bh = blockIdx.x, t = threadIdx.x;                  // 64 threads
    if (t < 32) qs[t] = qp[bh * 32 + t];
    __syncthreads();
    float s = 0.f;
    #pragma unroll
    for (int d = 0; d < 32; d++) s += qs[d] * kh[((bh * 32 + d) << 6) + t];
    sc[t] = s;
    __syncthreads();
    if (t == 0) {
        for (int it = 0; it < 16; it++) {
            float best = -3.4e38f; int bi = 0;
            for (int h = 0; h < 64; h++) if (sc[h] > best) { best = sc[h]; bi = h; }
            topH[bh * 16 + it] = bi; sc[bi] = -3.4e38f;
        }
    }
}

// ---------------- gather selected rows of k,v -> kg/vg [bh][d][16][64] -----------------
__global__ __launch_bounds__(256) void gather_rows_kernel(const float* __restrict__ qkv,
                                                          const int* __restrict__ topH,
                                                          float* __restrict__ kg,
                                                          float* __restrict__ vg)
{
    long i = (long)blockIdx.x * 256 + threadIdx.x;          // 64*32*16*64
    int w = i & 63; long r = i >> 6; int t = (int)(r & 15); r >>= 4;
    int d = (int)(r & 31); int bh = (int)(r >> 5);
    int b = bh >> 3, hh = bh & 7;
    int h = topH[bh * 16 + t];
    long base = (long)b * 768 * HW + (long)(hh * 32 + d) * HW + (long)h * WID + w;
    kg[i] = qkv[base + 256L * HW];
    vg[i] = qkv[base + 512L * HW];
}

// ---------------- score_c + top-16 columns ----------------
__global__ void topw_kernel(const float* __restrict__ qp, const float* __restrict__ kg,
                            int* __restrict__ topW)
{
    __shared__ float sc[64]; __shared__ float qs[32];
    int bh = blockIdx.x, t = threadIdx.x;                  // t = w, 64 threads
    if (t < 32) qs[t] = qp[bh * 32 + t];
    __syncthreads();
    float s = 0.f;
    for (int d = 0; d < 32; d++) {
        float colsum = 0.f;
        #pragma unroll
        for (int i = 0; i < 16; i++)
            colsum += kg[(((long)(bh * 32 + d) * 16) + i) * 64 + t];
        s += qs[d] * colsum;
    }
    sc[t] = s;
    __syncthreads();
    if (t == 0) {
        for (int it = 0; it < 16; it++) {
            float best = -3.4e38f; int bi = 0;
            for (int w = 0; w < 64; w++) if (sc[w] > best) { best = sc[w]; bi = w; }
            topW[bh * 16 + it] = bi; sc[bi] = -3.4e38f;
        }
    }
}

// ---------------- build kf/vf [bh][j][d2] as bf16x2, j = i*16 + jw ----------------
__global__ __launch_bounds__(256) void build_kv_kernel(const float* __restrict__ kg,
                                                       const float* __restrict__ vg,
                                                       const int* __restrict__ topW,
                                                       uint32_t* __restrict__ kf,
                                                       uint32_t* __restrict__ vf)
{
    int i = blockIdx.x * 256 + threadIdx.x;   // 64*256*16 = 262144
    int d2 = i & 15; int j = (i >> 4) & 255; int bh = i >> 12;
    int ti = j >> 4, jw = j & 15;
    int w = topW[bh * 16 + jw];
    long src = (((long)(bh * 32 + 2 * d2) * 16) + ti) * 64 + w;
    __nv_bfloat162 kk = __floats2bfloat162_rn(kg[src], kg[src + 1024]);
    __nv_bfloat162 vv = __floats2bfloat162_rn(vg[src], vg[src + 1024]);
    kf[i] = *(uint32_t*)&kk;
    vf[i] = *(uint32_t*)&vv;
}

// ---------------- fused sparse attention: softmax(Q Kf^T) Vf, bf16 K/V ----------------
__device__ __forceinline__ float2 bf2f(uint32_t u)
{
    __nv_bfloat162 h = *reinterpret_cast<__nv_bfloat162*>(&u);
    return __bfloat1622float2(h);
}

__global__ __launch_bounds__(128) void attn_kernel(const float* __restrict__ qkv,
                                                   const uint32_t* __restrict__ kf,
                                                   const uint32_t* __restrict__ vf,
                                                   float* __restrict__ out)
{
    __shared__ uint32_t kfs[128 * 16];
    __shared__ uint32_t vfs[128 * 16];
    int bh = blockIdx.y;
    int b = bh >> 3, hh = bh & 7;
    int p = blockIdx.x * 128 + threadIdx.x;
    const float* qb = qkv + (long)b * 768 * HW + (long)(hh * 32) * HW + p;
    float q[32], acc[32];
    #pragma unroll
    for (int d = 0; d < 32; d++) { q[d] = qb[(long)d * HW]; acc[d] = 0.f; }
    float l = 0.f;
    for (int ch = 0; ch < 2; ch++) {
        const uint4* kc = (const uint4*)(kf + ((long)bh * NKEY + ch * 128) * 16);
        const uint4* vc = (const uint4*)(vf + ((long)bh * NKEY + ch * 128) * 16);
        #pragma unroll
        for (int i = 0; i < 4; i++) {
            ((uint4*)kfs)[threadIdx.x + i * 128] = kc[threadIdx.x + i * 128];
            ((uint4*)vfs)[threadIdx.x + i * 128] = vc[threadIdx.x + i * 128];
        }
        __syncthreads();
        for (int j = 0; j < 128; j++) {
            const uint32_t* kk = &kfs[j * 16];
            float s = 0.f;
            #pragma unroll
            for (int d2 = 0; d2 < 16; d2++) {
                float2 f = bf2f(kk[d2]);
                s = fmaf(f.x, q[2 * d2], s);
                s = fmaf(f.y, q[2 * d2 + 1], s);
            }
            float e = __expf(s);
            l += e;
            const uint32_t* vv = &vfs[j * 16];
            #pragma unroll
            for (int d2 = 0; d2 < 16; d2++) {
                float2 f = bf2f(vv[d2]);
                acc[2 * d2]     = fmaf(e, f.x, acc[2 * d2]);
                acc[2 * d2 + 1] = fmaf(e, f.y, acc[2 * d2 + 1]);
            }
        }
        __syncthreads();
    }
    float inv = 1.f / l;
    float* ob = out + (long)b * CDIM * HW + (long)(hh * 32) * HW + p;
    #pragma unroll
    for (int d = 0; d < 32; d++) ob[(long)d * HW] = acc[d] * inv;
}

// ---------------- depthwise 3x3 SAME (small branch, writes into cat) ----------------
__global__ __launch_bounds__(256) void dwconv_kernel(const float* __restrict__ in,
                                                     const float* __restrict__ w,
                                                     const float* __restrict__ bias,
                                                     float* __restrict__ out,
                                                     int C, long inBS, long outBS, int chanOff)
{
    int idx = blockIdx.x;
    int yt = idx & 15; idx >>= 4;
    int c = idx % C; int b = idx / C;
    int x = threadIdx.x & 63;
    int y = yt * 4 + (threadIdx.x >> 6);
    const float* ip = in + (long)b * inBS + (long)c * HW;
    const float* wp = w + c * 9;
    float s = bias[c];
    #pragma unroll
    for (int dy = 0; dy < 3; dy++) {
        int yy = y + dy - 1;
        if (yy < 0 || yy > 63) continue;
        #pragma unroll
        for (int dx = 0; dx < 3; dx++) {
            int xx = x + dx - 1;
            if (xx < 0 || xx > 63) continue;
            s += wp[dy * 3 + dx] * ip[yy * 64 + xx];
        }
    }
    out[(long)b * outBS + (long)(chanOff + c) * HW + y * 64 + x] = s;
}

// ---------------- gelu ----------------
__device__ __forceinline__ float gelu_exact(float u)
{
    return 0.5f * u * (1.f + erff(u * 0.7071067811865476f));
}

// ---------------- fused dwconv3x3 + instnorm + gelu + add:  h = hg + gelu(IN(dw(hg)))
// one block per (b,c) row; channel tile staged in smem.
__global__ __launch_bounds__(256) void dwin_kernel(const float* __restrict__ hg,
                                                   const float* __restrict__ w,
                                                   const float* __restrict__ bias,
                                                   float* __restrict__ out)
{
    __shared__ float tile[HW];
    __shared__ float red[16];
    long row = blockIdx.x;
    int c = (int)(row & (FFI - 1));
    int t = threadIdx.x;
    const float4* src = (const float4*)(hg + row * HW);
    #pragma unroll
    for (int i = 0; i < 4; i++) ((float4*)tile)[t + i * 256] = src[t + i * 256];
    float wr[9];
    #pragma unroll
    for (int i = 0; i < 9; i++) wr[i] = w[c * 9 + i];
    float bb = bias[c];
    __syncthreads();

    float r[16];
    float s = 0.f, s2 = 0.f;
    #pragma unroll
    for (int i = 0; i < 16; i++) {
        int px = t + i * 256;
        int y = px >> 6, x = px & 63;
        float a = bb;
        #pragma unroll
        for (int dy = 0; dy < 3; dy++) {
            int yy = y + dy - 1;
            if (yy < 0 || yy > 63) continue;
            #pragma unroll
            for (int dx = 0; dx < 3; dx++) {
                int xx = x + dx - 1;
                if (xx < 0 || xx > 63) continue;
                a += wr[dy * 3 + dx] * tile[yy * 64 + xx];
            }
        }
        r[i] = a; s += a; s2 += a * a;
    }
    #pragma unroll
    for (int o = 16; o > 0; o >>= 1) {
        s  += __shfl_xor_sync(0xffffffffu, s, o);
        s2 += __shfl_xor_sync(0xffffffffu, s2, o);
    }
    if ((t & 31) == 0) { red[t >> 5] = s; red[8 + (t >> 5)] = s2; }
    __syncthreads();
    if (t == 0) {
        float a = 0.f, b2 = 0.f;
        for (int i = 0; i < 8; i++) { a += red[i]; b2 += red[8 + i]; }
        red[0] = a; red[8] = b2;
    }
    __syncthreads();
    float mean = red[0] * (1.f / HW);
    float var  = red[8] * (1.f / HW) - mean * mean;
    float inv  = rsqrtf(var + 1e-5f);
    float* ob = out + row * HW;
    #pragma unroll
    for (int i = 0; i < 16; i++) {
        int px = t + i * 256;
        ob[px] = tile[px] + gelu_exact((r[i] - mean) * inv);
    }
}

// ---------------- instance norm (+gelu) ----------------
template <int MODE>  // 0: norm; 1: gelu(norm)
__global__ __launch_bounds__(256) void instnorm_kernel(const float* __restrict__ in,
                                                       float* __restrict__ out)
{
    __shared__ float sm[16];
    long row = blockIdx.x;
    const float4* p = (const float4*)(in + row * HW);
    int t = threadIdx.x;
    float4 v[4];
    float s = 0.f, s2 = 0.f;
    #pragma unroll
    for (int i = 0; i < 4; i++) {
        v[i] = p[t + i * 256];
        s  += v[i].x + v[i].y + v[i].z + v[i].w;
        s2 += v[i].x * v[i].x + v[i].y * v[i].y + v[i].z * v[i].z + v[i].w * v[i].w;
    }
    #pragma unroll
    for (int o = 16; o > 0; o >>= 1) {
        s  += __shfl_xor_sync(0xffffffffu, s, o);
        s2 += __shfl_xor_sync(0xffffffffu, s2, o);
    }
    if ((t & 31) == 0) { sm[t >> 5] = s; sm[8 + (t >> 5)] = s2; }
    __syncthreads();
    if (t == 0) {
        float a = 0.f, b2 = 0.f;
        for (int i = 0; i < 8; i++) { a += sm[i]; b2 += sm[8 + i]; }
        sm[0] = a; sm[8] = b2;
    }
    __syncthreads();
    float mean = sm[0] * (1.f / HW);
    float var  = sm[8] * (1.f / HW) - mean * mean;
    float inv  = rsqrtf(var + 1e-5f);
    float4* op = (float4*)(out + row * HW);
    #pragma unroll
    for (int i = 0; i < 4; i++) {
        float4 u = v[i];
        u.x = (u.x - mean) * inv; u.y = (u.y - mean) * inv;
        u.z = (u.z - mean) * inv; u.w = (u.w - mean) * inv;
        if (MODE >= 1) {
            u.x = gelu_exact(u.x); u.y = gelu_exact(u.y);
            u.z = gelu_exact(u.z); u.w = gelu_exact(u.w);
        }
        op[t + i * 256] = u;
    }
}

// ---------------- host launcher ----------------
extern "C" void kernel_launch(void* const* d_in, const int* in_sizes, int n_in,
                              void* d_out, int out_size)
{
    (void)in_sizes; (void)n_in; (void)out_size;
    const float* x      = (const float*)d_in[0];
    const float* ln_g   = (const float*)d_in[1];
    const float* ln_b   = (const float*)d_in[2];
    const float* w_qkv  = (const float*)d_in[3];
    const float* w_out  = (const float*)d_in[4];
    const float* b_out  = (const float*)d_in[5];
    const float* w_dw   = (const float*)d_in[6];
    const float* b_dw   = (const float*)d_in[7];
    const float* w_comb = (const float*)d_in[8];
    const float* b_comb = (const float*)d_in[9];
    const float* w_ff1  = (const float*)d_in[10];
    const float* b_ff1  = (const float*)d_in[11];
    const float* w_ffdw = (const float*)d_in[12];
    const float* b_ffdw = (const float*)d_in[13];
    const float* w_ff2  = (const float*)d_in[14];
    const float* b_ff2  = (const float*)d_in[15];
    float* out = (float*)d_out;

    void *p;
    cudaGetSymbolAddress(&p, g_xn);   float* xn   = (float*)p;
    cudaGetSymbolAddress(&p, g_qkv);  float* qkv  = (float*)p;
    cudaGetSymbolAddress(&p, g_attn); float* attn = (float*)p;
    cudaGetSymbolAddress(&p, g_cat);  float* cat  = (float*)p;
    cudaGetSymbolAddress(&p, g_ao);   float* ao   = (float*)p;
    cudaGetSymbolAddress(&p, g_h);    float* h    = (float*)p;
    cudaGetSymbolAddress(&p, g_hg);   float* hg   = (float*)p;
    cudaGetSymbolAddress(&p, g_kg);   float* kg   = (float*)p;
    cudaGetSymbolAddress(&p, g_vg);   float* vg   = (float*)p;
    cudaGetSymbolAddress(&p, g_kf);   uint32_t* kf = (uint32_t*)p;
    cudaGetSymbolAddress(&p, g_vf);   uint32_t* vf = (uint32_t*)p;
    cudaGetSymbolAddress(&p, g_qp);   float* qp   = (float*)p;
    cudaGetSymbolAddress(&p, g_kh);   float* kh   = (float*)p;
    cudaGetSymbolAddress(&p, g_topH); int*   topH = (int*)p;
    cudaGetSymbolAddress(&p, g_topW); int*   topW = (int*)p;

    cudaFuncSetAttribute(tgemm_kernel<1>, cudaFuncAttributeMaxDynamicSharedMemorySize,
                         TGEMM_SMEM(1));
    cudaFuncSetAttribute(tgemm_kernel<0>, cudaFuncAttributeMaxDynamicSharedMemorySize,
                         TGEMM_SMEM(0));

    // 1. channel layernorm
    ln_kernel<<<128, 256>>>(x, ln_g, ln_b, xn);
    // 2. qkv projection (3xTF32: protects downstream top-k selection)
    tgemm_kernel<1><<<dim3(32, 6, BD), 256, TGEMM_SMEM(1)>>>(w_qkv, xn, qkv, 768, HW, 256,
                                           (long)CDIM * HW, (long)768 * HW,
                                           nullptr, nullptr, 0);
    // 3. l2-normalize q,k along W (in place)
    l2norm_kernel<<<32768, 256>>>(qkv);
    // 4. probes + top-k selection
    qprobe_kernel<<<2048, 256>>>(qkv, qp);
    kheight_kernel<<<16384, 256>>>(qkv, kh);
    toph_kernel<<<64, 64>>>(qp, kh, topH);
    gather_rows_kernel<<<8192, 256>>>(qkv, topH, kg, vg);
    topw_kernel<<<64, 64>>>(qp, kg, topW);
    build_kv_kernel<<<1024, 256>>>(kg, vg, topW, kf, vf);
    // 5. fused sparse attention (bf16 K/V)
    attn_kernel<<<dim3(32, NBH), 128>>>(qkv, kf, vf, attn);
    // 6. out-proj into concat buffer rows [0,256)
    tgemm_kernel<1><<<dim3(32, 2, BD), 256, TGEMM_SMEM(1)>>>(w_out, attn, cat, 256, HW, 256,
                                           (long)CDIM * HW, (long)512 * HW,
                                           b_out, nullptr, 0);
    // 7. dwconv branch into concat buffer rows [256,512)
    dwconv_kernel<<<BD * 256 * 16, 256>>>(x, w_dw, b_dw, cat, 256,
                                          (long)CDIM * HW, (long)512 * HW, 256);
    // 8. combine (K=512) + bias + residual x
    tgemm_kernel<1><<<dim3(32, 2, BD), 256, TGEMM_SMEM(1)>>>(w_comb, cat, ao, 256, HW, 512,
                                           (long)512 * HW, (long)CDIM * HW,
                                           b_comb, x, (long)CDIM * HW);
    // 9. ff1 (single-pass TF32)
    tgemm_kernel<0><<<dim3(32, 8, BD), 256, TGEMM_SMEM(0)>>>(w_ff1, ao, h, FFI, HW, 256,
                                           (long)CDIM * HW, (long)FFI * HW,
                                           b_ff1, nullptr, 0);
    // 10. hg = gelu(instnorm(h))
    instnorm_kernel<1><<<BD * FFI, 256>>>(h, hg);
    // 11+12. h = hg + gelu(instnorm(dwconv(hg)))  -- fused
    dwin_kernel<<<BD * FFI, 256>>>(hg, w_ffdw, b_ffdw, h);
    // 13. ff2 (single-pass TF32; reuse xn buffer for output)
    tgemm_kernel<0><<<dim3(32, 2, BD), 256, TGEMM_SMEM(0)>>>(w_ff2, h, xn, 256, HW, 1024,
                                           (long)FFI * HW, (long)CDIM * HW,
                                           b_ff2, nullptr, 0);
    // 14. final instance norm -> d_out
    instnorm_kernel<0><<<BD * CDIM, 256>>>(xn, out);
}